// round 1
// baseline (speedup 1.0000x reference)
#include <cuda_runtime.h>
#include <math.h>
#include <stdint.h>

// ---------------- problem constants ----------------
#define NTOT   65536            // 16*64*64 tokens
#define KCB    2048             // codebook entries
#define DIM    256              // embedding dim
#define BATCH  16
#define HW     4096             // 64*64
#define DHW    1048576          // 256*4096

// output layout (element offsets in f32 units, concat of reference tuple)
#define OFF_LOSS 0LL
#define OFF_QOUT 1LL
#define OFF_PERP 16777217LL
#define OFF_ENC  16777218LL
#define OFF_CS   150994946LL
#define OFF_EMAW 150996994LL
#define OFF_W    151521282LL

static const float DECAYF = 0.99f;
static const float OMD    = (float)(1.0 - 0.99);   // (1 - decay) as in reference
static const float EPSF   = 1e-5f;

// ---------------- device scratch (no allocations allowed) ----------------
__device__ float g_wnorm[KCB];
__device__ int   g_counts[KCB];
__device__ int   g_idx[NTOT];
__device__ float g_dw[KCB * DIM];
__device__ float g_loss;

// packed fp32x2 FMA (sm_100+)
__device__ __forceinline__ void fma2(unsigned long long &acc,
                                     unsigned long long a,
                                     unsigned long long b) {
    asm("fma.rn.f32x2 %0, %1, %2, %0;" : "+l"(acc) : "l"(a), "l"(b));
}

// ---------------- init scratch ----------------
__global__ void k_init() {
    int i = blockIdx.x * 256 + threadIdx.x;      // grid covers 524288
    g_dw[i] = 0.0f;
    if (i < KCB) g_counts[i] = 0;
    if (i == 0)  g_loss = 0.0f;
}

// ---------------- codebook norms ----------------
__global__ void k_wnorm(const float* __restrict__ weight) {
    int warp = threadIdx.x >> 5, lane = threadIdx.x & 31;
    int k = blockIdx.x * 8 + warp;               // grid 256 x 256 threads
    const float* row = weight + (size_t)k * DIM;
    float s = 0.0f;
    #pragma unroll
    for (int d = lane; d < DIM; d += 32) { float v = row[d]; s += v * v; }
    #pragma unroll
    for (int o = 16; o > 0; o >>= 1) s += __shfl_down_sync(0xffffffffu, s, o);
    if (lane == 0) g_wnorm[k] = s;
}

// ---------------- argmin over codebook (fp32, packed f32x2 FMA) ----------------
// 1024 blocks x 256 threads. Block: 64 queries x all 2048 codes.
// thread (tx=lane, ty=warp): queries {tx, tx+32}; per k-tile codes {ty*16+j}.
// smem: xs[64][260] (q-major, full D, d-contiguous for f32x2)  +  ws[128][36].
__global__ void __launch_bounds__(256, 2)
k_argmin(const float* __restrict__ z, const float* __restrict__ weight) {
    extern __shared__ float sm[];
    float* xs = sm;                 // 64*260 = 16640 floats
    float* ws = sm + 64 * 260;      // 128*36 = 4608 floats

    const int tid = threadIdx.x;
    const int tx = tid & 31, ty = tid >> 5;
    const int n0 = blockIdx.x * 64;
    const int b  = n0 >> 12;
    const int sp0 = n0 & 4095;
    const float* zb = z + (size_t)b * DHW + sp0;

    // load + transpose x tile: xs[q][d], q=0..63, d=0..255
    #pragma unroll
    for (int p = 0; p < 16; ++p) {
        int lin = tid + p * 256;
        int q = lin & 63, dq4 = lin >> 6;          // dq4 in [0,64)
        float4 v;
        v.x = zb[(dq4 * 4 + 0) * HW + q];
        v.y = zb[(dq4 * 4 + 1) * HW + q];
        v.z = zb[(dq4 * 4 + 2) * HW + q];
        v.w = zb[(dq4 * 4 + 3) * HW + q];
        *(float4*)(xs + q * 260 + dq4 * 4) = v;
    }
    __syncthreads();

    float minv0 = 3.4e38f, minv1 = 3.4e38f;
    int   mini0 = 0,       mini1 = 0;

    for (int kt = 0; kt < 16; ++kt) {
        const int kbase = kt * 128;
        unsigned long long acc0[16], acc1[16];
        #pragma unroll
        for (int j = 0; j < 16; ++j) { acc0[j] = 0ULL; acc1[j] = 0ULL; }

        for (int dc = 0; dc < 8; ++dc) {
            __syncthreads();   // previous-iteration readers done before overwrite
            // stage 128 codes x 32 dims of weight
            #pragma unroll
            for (int p = 0; p < 4; ++p) {
                int lin = tid + p * 256;
                int kk = lin >> 3, d4 = lin & 7;
                float4 v = *(const float4*)(weight + (size_t)(kbase + kk) * DIM + dc * 32 + d4 * 4);
                *(float4*)(ws + kk * 36 + d4 * 4) = v;
            }
            __syncthreads();
            #pragma unroll
            for (int dq = 0; dq < 8; ++dq) {
                const ulonglong2 xa = *(const ulonglong2*)(xs + tx * 260 + dc * 32 + dq * 4);
                const ulonglong2 xb = *(const ulonglong2*)(xs + (tx + 32) * 260 + dc * 32 + dq * 4);
                #pragma unroll
                for (int j = 0; j < 16; ++j) {
                    const ulonglong2 wv = *(const ulonglong2*)(ws + (ty * 16 + j) * 36 + dq * 4);
                    fma2(acc0[j], xa.x, wv.x);
                    fma2(acc0[j], xa.y, wv.y);
                    fma2(acc1[j], xb.x, wv.x);
                    fma2(acc1[j], xb.y, wv.y);
                }
            }
        }
        // fold tile into running argmin: score = ||w||^2 - 2 x.w
        #pragma unroll
        for (int j = 0; j < 16; ++j) {
            int k = kbase + ty * 16 + j;
            float wn = g_wnorm[k];
            float2 a0 = *(float2*)&acc0[j];
            float2 a1 = *(float2*)&acc1[j];
            float s0 = wn - 2.0f * (a0.x + a0.y);
            float s1 = wn - 2.0f * (a1.x + a1.y);
            if (s0 < minv0) { minv0 = s0; mini0 = k; }
            if (s1 < minv1) { minv1 = s1; mini1 = k; }
        }
    }

    // cross-warp reduction per query (tie -> lowest k, matching jnp.argmin)
    __syncthreads();
    float* rv = ws;
    int*   ri = (int*)(ws + 512);
    rv[tx * 8 + ty] = minv0;         ri[tx * 8 + ty] = mini0;
    rv[(tx + 32) * 8 + ty] = minv1;  ri[(tx + 32) * 8 + ty] = mini1;
    __syncthreads();
    if (tid < 64) {
        float bv = rv[tid * 8]; int bi = ri[tid * 8];
        #pragma unroll
        for (int t = 1; t < 8; ++t) {
            float v = rv[tid * 8 + t]; int ix = ri[tid * 8 + t];
            if (v < bv || (v == bv && ix < bi)) { bv = v; bi = ix; }
        }
        g_idx[n0 + tid] = bi;
        atomicAdd(&g_counts[bi], 1);
    }
}

// ---------------- quantize: q_out, encodings ones, loss, dw scatter ----------------
// 1024 blocks (one per (b,h) row) x 256 threads. Weight rows staged in smem so
// gather reads and q_out writes are both coalesced.
__global__ void k_quant(const float* __restrict__ z,
                        const float* __restrict__ weight,
                        float* __restrict__ out) {
    extern __shared__ float wrow[];              // 64 * 257 floats
    __shared__ int   idx_s[64];
    __shared__ float lred[256];

    const int tid = threadIdx.x;
    const int blk = blockIdx.x;
    const int b = blk >> 6, h = blk & 63;
    const int n0 = b * HW + h * 64;

    if (tid < 64) {
        int ix = g_idx[n0 + tid];
        idx_s[tid] = ix;
        out[OFF_ENC + (long long)(n0 + tid) * KCB + ix] = 1.0f;   // region pre-zeroed
    }
    __syncthreads();

    // stage the 64 gathered codebook rows (coalesced reads)
    int wp = tid >> 5, lane = tid & 31;
    for (int r = wp; r < 64; r += 8) {
        const float4* src = (const float4*)(weight + (size_t)idx_s[r] * DIM);
        for (int d4 = lane; d4 < 64; d4 += 32) {
            float4 v = src[d4];
            float* dst = wrow + r * 257 + d4 * 4;
            dst[0] = v.x; dst[1] = v.y; dst[2] = v.z; dst[3] = v.w;
        }
    }
    __syncthreads();

    const int w = tid & 63, dg = tid >> 6;
    const float* zbp = z + (size_t)b * DHW + h * 64 + w;
    float*       qbp = out + OFF_QOUT + (size_t)b * DHW + h * 64 + w;
    float*       dwr = g_dw + (size_t)idx_s[w] * DIM;
    const float* wr  = wrow + w * 257;

    float lacc = 0.0f;
    for (int s = 0; s < 16; ++s) {
        int d0 = dg * 4 + s * 16;
        #pragma unroll
        for (int c = 0; c < 4; ++c) {
            int d = d0 + c;
            float x  = zbp[(size_t)d * HW];
            float qv = wr[d];
            qbp[(size_t)d * HW] = qv;
            float df = qv - x;
            lacc += df * df;
            atomicAdd(&dwr[d], x);
        }
    }

    lred[tid] = lacc;
    __syncthreads();
    #pragma unroll
    for (int st = 128; st > 0; st >>= 1) {
        if (tid < st) lred[tid] += lred[tid + st];
        __syncthreads();
    }
    if (tid == 0) atomicAdd(&g_loss, lred[0]);
}

// ---------------- cluster-size stats, perplexity, loss finalize ----------------
__global__ void k_stats(const float* __restrict__ ecs, float* __restrict__ out) {
    __shared__ float sn[1024];
    __shared__ float sh[1024];
    int t = threadIdx.x;
    float c0 = (float)g_counts[t];
    float c1 = (float)g_counts[t + 1024];
    float cs0 = ecs[t] * DECAYF + OMD * c0;
    float cs1 = ecs[t + 1024] * DECAYF + OMD * c1;
    float p0 = c0 / 65536.0f, p1 = c1 / 65536.0f;
    sn[t] = cs0 + cs1;
    sh[t] = p0 * logf(p0 + 1e-10f) + p1 * logf(p1 + 1e-10f);
    __syncthreads();
    #pragma unroll
    for (int st = 512; st > 0; st >>= 1) {
        if (t < st) { sn[t] += sn[t + st]; sh[t] += sh[t + st]; }
        __syncthreads();
    }
    float n = sn[0];
    float denom = n + (float)KCB * EPSF;
    out[OFF_CS + t]        = (cs0 + EPSF) / denom * n;
    out[OFF_CS + t + 1024] = (cs1 + EPSF) / denom * n;
    if (t == 0) {
        out[OFF_PERP] = expf(-sh[0]);
        out[OFF_LOSS] = 0.25f * g_loss / 16777216.0f;
    }
}

// ---------------- EMA weight update ----------------
__global__ void k_ema(const float* __restrict__ emaw, float* __restrict__ out) {
    int i = blockIdx.x * 256 + threadIdx.x;      // grid covers 524288
    float e = emaw[i] * DECAYF + OMD * g_dw[i];
    out[OFF_EMAW + i] = e;
    out[OFF_W + i]    = e / out[OFF_CS + (i >> 8)];
}

// ---------------- launch ----------------
extern "C" void kernel_launch(void* const* d_in, const int* in_sizes, int n_in,
                              void* d_out, int out_size) {
    const float* z    = (const float*)d_in[0];   // [16,256,64,64]
    const float* wgt  = (const float*)d_in[1];   // [2048,256]
    const float* ecs  = (const float*)d_in[2];   // [2048]
    const float* emaw = (const float*)d_in[3];   // [2048,256]
    float* out = (float*)d_out;

    const int SMEM_ARGMIN = (64 * 260 + 128 * 36) * 4;  // 84992 B
    const int SMEM_QUANT  = (64 * 257) * 4;             // 65792 B
    cudaFuncSetAttribute(k_argmin, cudaFuncAttributeMaxDynamicSharedMemorySize, SMEM_ARGMIN);
    cudaFuncSetAttribute(k_quant,  cudaFuncAttributeMaxDynamicSharedMemorySize, SMEM_QUANT);

    // zero the one-hot encodings region (536 MB)
    cudaMemsetAsync(out + OFF_ENC, 0, (size_t)NTOT * KCB * sizeof(float), 0);

    k_init  <<<2048, 256>>>();
    k_wnorm <<<256, 256>>>(wgt);
    k_argmin<<<1024, 256, SMEM_ARGMIN>>>(z, wgt);
    k_quant <<<1024, 256, SMEM_QUANT>>>(z, wgt, out);
    k_stats <<<1, 1024>>>(ecs, out);
    k_ema   <<<2048, 256>>>(emaw, out);
}

// round 5
// speedup vs baseline: 2.1929x; 2.1929x over previous
#include <cuda_runtime.h>
#include <cuda_fp16.h>
#include <math.h>
#include <stdint.h>

// ---------------- problem constants ----------------
#define NTOT   65536
#define KCB    2048
#define DIM    256
#define HW     4096
#define DHW    1048576

#define OFF_LOSS 0LL
#define OFF_QOUT 1LL
#define OFF_PERP 16777217LL
#define OFF_ENC  16777218LL
#define OFF_CS   150994946LL
#define OFF_EMAW 150996994LL
#define OFF_W    151521282LL

static const float DECAYF = 0.99f;
static const float OMD    = 0.01f;
static const float EPSF   = 1e-5f;

// ---------------- device scratch ----------------
__device__ __half g_Xh[NTOT * DIM];     // token-major fp16 x      (32MB)
__device__ __half g_Wh[KCB * DIM];      // code-major fp16 (-2w)   (1MB)
__device__ float  g_Xf[NTOT * DIM];     // token-major fp32 x      (64MB)
__device__ float  g_wnorm[KCB];
__device__ int    g_counts[KCB];
__device__ int    g_off[KCB];
__device__ int    g_cur[KCB];
__device__ int    g_perm[NTOT];
__device__ int    g_idx[NTOT];
__device__ int4   g_cand4[NTOT];        // 4 exact-rescore candidates per token (1MB)
__device__ float  g_dw[KCB * DIM];
__device__ float  g_loss;

// ---------------- helpers ----------------
__device__ __forceinline__ uint32_t smem_u32(const void* p) {
    uint32_t a;
    asm("{ .reg .u64 t; cvta.to.shared.u64 t, %1; cvt.u32.u64 %0, t; }" : "=r"(a) : "l"(p));
    return a;
}
__device__ __forceinline__ void cp16(uint32_t dst, const void* src) {
    asm volatile("cp.async.cg.shared.global [%0], [%1], 16;" :: "r"(dst), "l"(src) : "memory");
}
__device__ __forceinline__ void cp_commit() { asm volatile("cp.async.commit_group;" ::: "memory"); }

__device__ __forceinline__ void ldm4(uint32_t a, uint32_t r[4]) {
    asm volatile("ldmatrix.sync.aligned.m8n8.x4.shared.b16 {%0,%1,%2,%3}, [%4];"
                 : "=r"(r[0]), "=r"(r[1]), "=r"(r[2]), "=r"(r[3]) : "r"(a));
}
__device__ __forceinline__ void mma16816(float c[4], const uint32_t a[4],
                                         uint32_t b0, uint32_t b1) {
    asm volatile("mma.sync.aligned.m16n8k16.row.col.f32.f16.f16.f32 "
                 "{%0,%1,%2,%3},{%4,%5,%6,%7},{%8,%9},{%0,%1,%2,%3};"
                 : "+f"(c[0]), "+f"(c[1]), "+f"(c[2]), "+f"(c[3])
                 : "r"(a[0]), "r"(a[1]), "r"(a[2]), "r"(a[3]), "r"(b0), "r"(b1));
}

// ---------------- init ----------------
__global__ void k_init() {
    int i = blockIdx.x * 256 + threadIdx.x;   // 2048
    g_counts[i] = 0;
    if (i == 0) g_loss = 0.0f;
}

// ---------------- codebook prep: fp16(-2w) + norms ----------------
__global__ void k_prep_w(const float* __restrict__ weight) {
    int warp = threadIdx.x >> 5, lane = threadIdx.x & 31;
    int k = blockIdx.x * 8 + warp;               // 256 blocks
    float s = 0.0f;
    #pragma unroll
    for (int i = 0; i < 8; ++i) {
        int d = lane + i * 32;
        float v = weight[(size_t)k * DIM + d];
        g_Wh[(size_t)k * DIM + d] = __float2half(-2.0f * v);
        s += v * v;
    }
    #pragma unroll
    for (int o = 16; o > 0; o >>= 1) s += __shfl_down_sync(0xffffffffu, s, o);
    if (lane == 0) g_wnorm[k] = s;
}

// ---------------- x prep: transpose to token-major fp32 + fp16 ----------------
__global__ void k_prep_x(const float* __restrict__ z) {
    extern __shared__ float xs[];             // 64*260
    const int tid = threadIdx.x;
    const int n0 = blockIdx.x * 64;
    const int b = n0 >> 12, sp0 = n0 & 4095;
    const float* zb = z + (size_t)b * DHW + sp0;
    #pragma unroll
    for (int p = 0; p < 16; ++p) {
        int lin = tid + p * 256;
        int q = lin & 63, dq4 = lin >> 6;
        float4 v;
        v.x = zb[(dq4 * 4 + 0) * HW + q];
        v.y = zb[(dq4 * 4 + 1) * HW + q];
        v.z = zb[(dq4 * 4 + 2) * HW + q];
        v.w = zb[(dq4 * 4 + 3) * HW + q];
        *(float4*)(xs + q * 260 + dq4 * 4) = v;
    }
    __syncthreads();
    #pragma unroll
    for (int p = 0; p < 64; ++p) {
        int lin = tid + p * 256;
        int q = lin >> 8, d = lin & 255;
        float v = xs[q * 260 + d];
        size_t t = (size_t)(n0 + q);
        g_Xh[t * DIM + d] = __float2half(v);
        g_Xf[t * DIM + d] = v;
    }
}

// ---------------- HMMA argmin GEMM ----------------
// 512 CTAs x 256 thr (8 warps: 2m x 4n). CTA = 128 tokens x 2048 codes, K=256.
// A (128x256 fp16, 64KB) resident; B (128x256, 64KB) double-buffered cp.async.
// SMEM swizzle: 16B chunk c of row r stored at chunk (c ^ (r&7)).
#define SA  0
#define SB0 65536
#define SB1 131072
#define SMT 196608

__global__ void __launch_bounds__(256, 1)
k_gemm() {
    extern __shared__ char sm[];
    const uint32_t sb = smem_u32(sm);
    const int tid = threadIdx.x;
    const int lane = tid & 31, warp = tid >> 5;
    const int wm = warp & 1, wn = warp >> 1;
    const int n0 = blockIdx.x * 128;

    // A tile (group with B0)
    #pragma unroll
    for (int i = 0; i < 16; ++i) {
        int idx = tid + i * 256;                 // 4096 = 128 rows x 32 chunks
        int row = idx >> 5, ch = idx & 31;
        cp16(sb + SA + row * 512 + ((ch ^ (row & 7)) << 4),
             g_Xh + (size_t)(n0 + row) * DIM + ch * 8);
    }
    // B tile 0
    #pragma unroll
    for (int i = 0; i < 16; ++i) {
        int idx = tid + i * 256;
        int row = idx >> 5, ch = idx & 31;
        cp16(sb + SB0 + row * 512 + ((ch ^ (row & 7)) << 4),
             g_Wh + (size_t)row * DIM + ch * 8);
    }
    cp_commit();
    // B tile 1
    #pragma unroll
    for (int i = 0; i < 16; ++i) {
        int idx = tid + i * 256;
        int row = idx >> 5, ch = idx & 31;
        cp16(sb + SB1 + row * 512 + ((ch ^ (row & 7)) << 4),
             g_Wh + (size_t)(128 + row) * DIM + ch * 8);
    }
    cp_commit();

    // per-thread top-2 for 8 owned token rows (mi*2 + h)
    float v1[8], v2[8];
    int   i1[8], i2[8];
    #pragma unroll
    for (int r = 0; r < 8; ++r) { v1[r] = 3.4e38f; v2[r] = 3.4e38f; i1[r] = 0; i2[r] = 0; }

    for (int nt = 0; nt < 16; ++nt) {
        if (nt < 15) asm volatile("cp.async.wait_group 1;" ::: "memory");
        else         asm volatile("cp.async.wait_group 0;" ::: "memory");
        __syncthreads();
        const uint32_t BB = sb + ((nt & 1) ? SB1 : SB0);

        float c[4][4][4];
        #pragma unroll
        for (int mi = 0; mi < 4; ++mi)
            #pragma unroll
            for (int ni = 0; ni < 4; ++ni)
                #pragma unroll
                for (int e = 0; e < 4; ++e) c[mi][ni][e] = 0.0f;

        #pragma unroll
        for (int ks = 0; ks < 16; ++ks) {
            uint32_t a[4][4];
            #pragma unroll
            for (int mi = 0; mi < 4; ++mi) {
                int row = wm * 64 + mi * 16 + (lane & 15);
                int ch = ks * 2 + (lane >> 4);
                ldm4(sb + SA + row * 512 + ((ch ^ (row & 7)) << 4), a[mi]);
            }
            // B: non-trans ldmatrix on code-major smem.
            // mats 0/1 = codes g*16+0..7 x (k-lo,k-hi); 2/3 = codes +8..15.
            uint32_t b[2][4];
            #pragma unroll
            for (int g = 0; g < 2; ++g) {
                int code = wn * 32 + g * 16 + ((lane & 16) >> 1) + (lane & 7);
                int ch = ks * 2 + ((lane >> 3) & 1);
                ldm4(BB + code * 512 + ((ch ^ (code & 7)) << 4), b[g]);
            }
            #pragma unroll
            for (int mi = 0; mi < 4; ++mi)
                #pragma unroll
                for (int ni = 0; ni < 4; ++ni)
                    mma16816(c[mi][ni], a[mi], b[ni >> 1][(ni & 1) * 2],
                             b[ni >> 1][(ni & 1) * 2 + 1]);
        }

        // fold: score = wnorm + acc  (acc = x . (-2w))
        #pragma unroll
        for (int ni = 0; ni < 4; ++ni) {
            int col = nt * 128 + wn * 32 + ni * 8 + (lane & 3) * 2;
            float2 wn2 = *(const float2*)&g_wnorm[col];
            #pragma unroll
            for (int mi = 0; mi < 4; ++mi) {
                #pragma unroll
                for (int h = 0; h < 2; ++h) {
                    int r = mi * 2 + h;
                    float s0 = wn2.x + c[mi][ni][h * 2];
                    float s1 = wn2.y + c[mi][ni][h * 2 + 1];
                    if (s0 < v1[r]) { v2[r] = v1[r]; i2[r] = i1[r]; v1[r] = s0; i1[r] = col; }
                    else if (s0 < v2[r]) { v2[r] = s0; i2[r] = col; }
                    if (s1 < v1[r]) { v2[r] = v1[r]; i2[r] = i1[r]; v1[r] = s1; i1[r] = col + 1; }
                    else if (s1 < v2[r]) { v2[r] = s1; i2[r] = col + 1; }
                }
            }
        }

        __syncthreads();
        if (nt + 2 < 16) {
            const uint32_t NB = sb + ((nt & 1) ? SB1 : SB0);
            #pragma unroll
            for (int i = 0; i < 16; ++i) {
                int idx = tid + i * 256;
                int row = idx >> 5, ch = idx & 31;
                cp16(NB + row * 512 + ((ch ^ (row & 7)) << 4),
                     g_Wh + (size_t)((nt + 2) * 128 + row) * DIM + ch * 8);
            }
            cp_commit();
        }
    }

    // ---- per-token merge: 16 threads x top-2 -> global top-4 (smem, stride 33) ----
    __syncthreads();
    float* cv = (float*)sm;                      // 128 * 33 floats
    int*   ci = (int*)(sm + 17408);              // 128 * 33 ints
    const int slot = wn * 4 + (lane & 3);        // 0..15
    #pragma unroll
    for (int mi = 0; mi < 4; ++mi)
        #pragma unroll
        for (int h = 0; h < 2; ++h) {
            int r = mi * 2 + h;
            int tloc = wm * 64 + mi * 16 + h * 8 + (lane >> 2);
            cv[tloc * 33 + slot * 2]     = v1[r];
            ci[tloc * 33 + slot * 2]     = i1[r];
            cv[tloc * 33 + slot * 2 + 1] = v2[r];
            ci[tloc * 33 + slot * 2 + 1] = i2[r];
        }
    __syncthreads();
    if (tid < 128) {
        float bv0 = 3.4e38f, bv1b = 3.4e38f, bv2b = 3.4e38f, bv3 = 3.4e38f;
        int   bx0 = 0, bx1 = 0, bx2 = 0, bx3 = 0;
        #pragma unroll
        for (int e = 0; e < 32; ++e) {
            float v = cv[tid * 33 + e];
            int   ix = ci[tid * 33 + e];
            if (v < bv3) {
                if (v < bv0) { bv3=bv2b; bx3=bx2; bv2b=bv1b; bx2=bx1; bv1b=bv0; bx1=bx0; bv0=v; bx0=ix; }
                else if (v < bv1b) { bv3=bv2b; bx3=bx2; bv2b=bv1b; bx2=bx1; bv1b=v; bx1=ix; }
                else if (v < bv2b) { bv3=bv2b; bx3=bx2; bv2b=v; bx2=ix; }
                else { bv3=v; bx3=ix; }
            }
        }
        g_cand4[n0 + tid] = make_int4(bx0, bx1, bx2, bx3);
    }
}

// ---------------- exact fp32 rescore of 4 candidates ----------------
__global__ void k_rescore(const float* __restrict__ weight) {
    const int warp = threadIdx.x >> 5, lane = threadIdx.x & 31;
    #pragma unroll
    for (int it = 0; it < 4; ++it) {
        int t = (blockIdx.x * 8 + warp) * 4 + it;
        int4 cc = g_cand4[t];
        int cand[4] = {cc.x, cc.y, cc.z, cc.w};
        float xv[8];
        #pragma unroll
        for (int i = 0; i < 8; ++i) xv[i] = g_Xf[(size_t)t * DIM + lane + 32 * i];
        float bs = 3.4e38f; int bi = 0x7fffffff;
        #pragma unroll
        for (int j = 0; j < 4; ++j) {
            int k = cand[j];
            float d = 0.0f;
            #pragma unroll
            for (int i = 0; i < 8; ++i)
                d += xv[i] * weight[(size_t)k * DIM + lane + 32 * i];
            #pragma unroll
            for (int o = 16; o > 0; o >>= 1) d += __shfl_xor_sync(0xffffffffu, d, o);
            float s = g_wnorm[k] - 2.0f * d;
            if (s < bs || (s == bs && k < bi)) { bs = s; bi = k; }
        }
        if (lane == 0) {
            g_idx[t] = bi;
            atomicAdd(&g_counts[bi], 1);
        }
    }
}

// ---------------- quantize: q_out + encodings + loss ----------------
__global__ void __launch_bounds__(256)
k_quant(const float* __restrict__ z, const float* __restrict__ weight,
        float* __restrict__ out) {
    __shared__ float wrow[64 * 67];
    __shared__ int   idx_s[64];
    __shared__ float lred[256];
    const int tid = threadIdx.x, blk = blockIdx.x;
    const int b = blk >> 6, h = blk & 63;
    const int n0 = b * HW + h * 64;
    if (tid < 64) {
        int ix = g_idx[n0 + tid];
        idx_s[tid] = ix;
        out[OFF_ENC + (long long)(n0 + tid) * KCB + ix] = 1.0f;
    }
    __syncthreads();
    const int w = tid & 63, dg = tid >> 6;
    const float* zbp = z + (size_t)b * DHW + h * 64 + w;
    float* qbp = out + OFF_QOUT + (size_t)b * DHW + h * 64 + w;
    float lacc = 0.0f;
    for (int c = 0; c < 4; ++c) {
        #pragma unroll
        for (int p = 0; p < 16; ++p) {
            int idx = tid + p * 256;
            int r = idx >> 6, d = idx & 63;
            wrow[r * 67 + d] = weight[(size_t)idx_s[r] * DIM + c * 64 + d];
        }
        __syncthreads();
        #pragma unroll
        for (int s = 0; s < 16; ++s) {
            int dl = dg * 16 + s;
            int d = c * 64 + dl;
            float x  = zbp[(size_t)d * HW];
            float qv = wrow[w * 67 + dl];
            qbp[(size_t)d * HW] = qv;
            float df = qv - x;
            lacc += df * df;
        }
        __syncthreads();
    }
    lred[tid] = lacc;
    __syncthreads();
    #pragma unroll
    for (int st = 128; st > 0; st >>= 1) {
        if (tid < st) lred[tid] += lred[tid + st];
        __syncthreads();
    }
    if (tid == 0) atomicAdd(&g_loss, lred[0]);
}

// ---------------- counting-sort for dw ----------------
__global__ void k_scan() {
    __shared__ int a[1024], bbuf[1024];
    int t = threadIdx.x;
    int c0 = g_counts[2 * t], c1 = g_counts[2 * t + 1];
    a[t] = c0 + c1;
    __syncthreads();
    int* src = a; int* dst = bbuf;
    for (int d = 1; d < 1024; d <<= 1) {
        int v = src[t] + ((t >= d) ? src[t - d] : 0);
        dst[t] = v;
        __syncthreads();
        int* tmp = src; src = dst; dst = tmp;
    }
    int incl = src[t];
    int e = incl - (c0 + c1);
    g_off[2 * t] = e;           g_cur[2 * t] = e;
    g_off[2 * t + 1] = e + c0;  g_cur[2 * t + 1] = e + c0;
}
__global__ void k_scatter() {
    int t = blockIdx.x * 256 + threadIdx.x;
    int ix = g_idx[t];
    int pos = atomicAdd(&g_cur[ix], 1);
    g_perm[pos] = t;
}
__global__ void k_dw() {
    const int k = blockIdx.x, tid = threadIdx.x;
    const int start = g_off[k], cnt = g_counts[k];
    float a0 = 0.0f, a1 = 0.0f;
    for (int i = 0; i < cnt; ++i) {
        int t = g_perm[start + i];
        a0 += g_Xf[(size_t)t * DIM + tid];
        a1 += g_Xf[(size_t)t * DIM + 128 + tid];
    }
    g_dw[(size_t)k * DIM + tid] = a0;
    g_dw[(size_t)k * DIM + 128 + tid] = a1;
}

// ---------------- stats ----------------
__global__ void k_stats(const float* __restrict__ ecs, float* __restrict__ out) {
    __shared__ float sn[1024];
    __shared__ float sh[1024];
    int t = threadIdx.x;
    float c0 = (float)g_counts[t];
    float c1 = (float)g_counts[t + 1024];
    float cs0 = ecs[t] * DECAYF + OMD * c0;
    float cs1 = ecs[t + 1024] * DECAYF + OMD * c1;
    float p0 = c0 / 65536.0f, p1 = c1 / 65536.0f;
    sn[t] = cs0 + cs1;
    sh[t] = p0 * logf(p0 + 1e-10f) + p1 * logf(p1 + 1e-10f);
    __syncthreads();
    #pragma unroll
    for (int st = 512; st > 0; st >>= 1) {
        if (t < st) { sn[t] += sn[t + st]; sh[t] += sh[t + st]; }
        __syncthreads();
    }
    float n = sn[0];
    float denom = n + (float)KCB * EPSF;
    out[OFF_CS + t]        = (cs0 + EPSF) / denom * n;
    out[OFF_CS + t + 1024] = (cs1 + EPSF) / denom * n;
    if (t == 0) {
        out[OFF_PERP] = expf(-sh[0]);
        out[OFF_LOSS] = 0.25f * g_loss / 16777216.0f;
    }
}

// ---------------- EMA update ----------------
__global__ void k_ema(const float* __restrict__ emaw, float* __restrict__ out) {
    int i = blockIdx.x * 256 + threadIdx.x;
    float e = emaw[i] * DECAYF + OMD * g_dw[i];
    out[OFF_EMAW + i] = e;
    out[OFF_W + i]    = e / out[OFF_CS + (i >> 8)];
}

// ---------------- launch ----------------
extern "C" void kernel_launch(void* const* d_in, const int* in_sizes, int n_in,
                              void* d_out, int out_size) {
    const float* z    = (const float*)d_in[0];
    const float* wgt  = (const float*)d_in[1];
    const float* ecs  = (const float*)d_in[2];
    const float* emaw = (const float*)d_in[3];
    float* out = (float*)d_out;

    cudaFuncSetAttribute(k_gemm,   cudaFuncAttributeMaxDynamicSharedMemorySize, SMT);
    cudaFuncSetAttribute(k_prep_x, cudaFuncAttributeMaxDynamicSharedMemorySize, 64 * 260 * 4);

    cudaMemsetAsync(out + OFF_ENC, 0, (size_t)NTOT * KCB * sizeof(float), 0);

    k_init   <<<8, 256>>>();
    k_prep_w <<<256, 256>>>(wgt);
    k_prep_x <<<1024, 256, 64 * 260 * 4>>>(z);
    k_gemm   <<<512, 256, SMT>>>();
    k_rescore<<<2048, 256>>>(wgt);
    k_quant  <<<1024, 256>>>(z, wgt, out);
    k_scan   <<<1, 1024>>>();
    k_scatter<<<256, 256>>>();
    k_dw     <<<2048, 128>>>();
    k_stats  <<<1, 1024>>>(ecs, out);
    k_ema    <<<2048, 256>>>(emaw, out);
}

// round 6
// speedup vs baseline: 2.4402x; 1.1128x over previous
#include <cuda_runtime.h>
#include <cuda_fp16.h>
#include <math.h>
#include <stdint.h>

// ---------------- problem constants ----------------
#define NTOT   65536
#define KCB    2048
#define DIM    256
#define HW     4096
#define DHW    1048576

#define OFF_LOSS 0LL
#define OFF_QOUT 1LL
#define OFF_PERP 16777217LL
#define OFF_ENC  16777218LL
#define OFF_CS   150994946LL
#define OFF_EMAW 150996994LL
#define OFF_W    151521282LL

static const float DECAYF = 0.99f;
static const float OMD    = 0.01f;
static const float EPSF   = 1e-5f;

// ---------------- device scratch ----------------
__device__ __half g_Xh[NTOT * DIM];     // token-major fp16 x      (32MB)
__device__ __half g_Wh[KCB * DIM];      // code-major fp16 (-2w)   (1MB)
__device__ float  g_Xf[NTOT * DIM];     // token-major fp32 x      (64MB)
__device__ float  g_wnorm[KCB];
__device__ int    g_counts[KCB];
__device__ int    g_off[KCB];
__device__ int    g_cur[KCB];
__device__ int    g_perm[NTOT];
__device__ int    g_idx[NTOT];
__device__ int4   g_cand4[NTOT];        // 4 exact-rescore candidates per token (1MB)
__device__ float  g_dw[KCB * DIM];
__device__ float  g_loss;

// ---------------- helpers ----------------
__device__ __forceinline__ uint32_t smem_u32(const void* p) {
    uint32_t a;
    asm("{ .reg .u64 t; cvta.to.shared.u64 t, %1; cvt.u32.u64 %0, t; }" : "=r"(a) : "l"(p));
    return a;
}
__device__ __forceinline__ void cp16(uint32_t dst, const void* src) {
    asm volatile("cp.async.cg.shared.global [%0], [%1], 16;" :: "r"(dst), "l"(src) : "memory");
}
__device__ __forceinline__ void cp_commit() { asm volatile("cp.async.commit_group;" ::: "memory"); }

__device__ __forceinline__ void ldm4(uint32_t a, uint32_t r[4]) {
    asm volatile("ldmatrix.sync.aligned.m8n8.x4.shared.b16 {%0,%1,%2,%3}, [%4];"
                 : "=r"(r[0]), "=r"(r[1]), "=r"(r[2]), "=r"(r[3]) : "r"(a));
}
__device__ __forceinline__ void mma16816(float c[4], const uint32_t a[4],
                                         uint32_t b0, uint32_t b1) {
    asm volatile("mma.sync.aligned.m16n8k16.row.col.f32.f16.f16.f32 "
                 "{%0,%1,%2,%3},{%4,%5,%6,%7},{%8,%9},{%0,%1,%2,%3};"
                 : "+f"(c[0]), "+f"(c[1]), "+f"(c[2]), "+f"(c[3])
                 : "r"(a[0]), "r"(a[1]), "r"(a[2]), "r"(a[3]), "r"(b0), "r"(b1));
}

// ---------------- init ----------------
__global__ void k_init() {
    int i = blockIdx.x * 256 + threadIdx.x;   // 2048
    g_counts[i] = 0;
    if (i == 0) g_loss = 0.0f;
}

// ---------------- codebook prep: fp16(-2w) + norms ----------------
__global__ void k_prep_w(const float* __restrict__ weight) {
    int warp = threadIdx.x >> 5, lane = threadIdx.x & 31;
    int k = blockIdx.x * 8 + warp;               // 256 blocks
    float s = 0.0f;
    #pragma unroll
    for (int i = 0; i < 8; ++i) {
        int d = lane + i * 32;
        float v = weight[(size_t)k * DIM + d];
        g_Wh[(size_t)k * DIM + d] = __float2half(-2.0f * v);
        s += v * v;
    }
    #pragma unroll
    for (int o = 16; o > 0; o >>= 1) s += __shfl_down_sync(0xffffffffu, s, o);
    if (lane == 0) g_wnorm[k] = s;
}

// ---------------- x prep: transpose to token-major fp32 + fp16 ----------------
__global__ void k_prep_x(const float* __restrict__ z) {
    extern __shared__ float xs[];             // 64*260
    const int tid = threadIdx.x;
    const int n0 = blockIdx.x * 64;
    const int b = n0 >> 12, sp0 = n0 & 4095;
    const float* zb = z + (size_t)b * DHW + sp0;
    #pragma unroll
    for (int p = 0; p < 16; ++p) {
        int lin = tid + p * 256;
        int q = lin & 63, dq4 = lin >> 6;
        float4 v;
        v.x = zb[(dq4 * 4 + 0) * HW + q];
        v.y = zb[(dq4 * 4 + 1) * HW + q];
        v.z = zb[(dq4 * 4 + 2) * HW + q];
        v.w = zb[(dq4 * 4 + 3) * HW + q];
        *(float4*)(xs + q * 260 + dq4 * 4) = v;
    }
    __syncthreads();
    #pragma unroll
    for (int p = 0; p < 64; ++p) {
        int lin = tid + p * 256;
        int q = lin >> 8, d = lin & 255;
        float v = xs[q * 260 + d];
        size_t t = (size_t)(n0 + q);
        g_Xh[t * DIM + d] = __float2half(v);
        g_Xf[t * DIM + d] = v;
    }
}

// ---------------- HMMA argmin GEMM ----------------
// 512 CTAs x 512 thr (16 warps: 2m x 8n). CTA = 128 tokens x 2048 codes, K=256.
// A (128x256 fp16, 64KB) resident; B (128x256, 64KB) double-buffered cp.async.
// Warp tile 64 tokens x 16 codes. SMEM swizzle: chunk c of row r at (c ^ (r&7)).
#define SA  0
#define SB0 65536
#define SB1 131072
#define SMT 196608

__global__ void __launch_bounds__(512, 1)
k_gemm() {
    extern __shared__ char sm[];
    const uint32_t sb = smem_u32(sm);
    const int tid = threadIdx.x;
    const int lane = tid & 31, warp = tid >> 5;
    const int wm = warp & 1, wn = warp >> 1;      // wm: token half, wn: 0..7
    const int n0 = blockIdx.x * 128;

    // A tile (grouped with B0)
    #pragma unroll
    for (int i = 0; i < 8; ++i) {
        int idx = tid + i * 512;                 // 4096 chunks
        int row = idx >> 5, ch = idx & 31;
        cp16(sb + SA + row * 512 + ((ch ^ (row & 7)) << 4),
             g_Xh + (size_t)(n0 + row) * DIM + ch * 8);
    }
    // B tile 0
    #pragma unroll
    for (int i = 0; i < 8; ++i) {
        int idx = tid + i * 512;
        int row = idx >> 5, ch = idx & 31;
        cp16(sb + SB0 + row * 512 + ((ch ^ (row & 7)) << 4),
             g_Wh + (size_t)row * DIM + ch * 8);
    }
    cp_commit();
    // B tile 1
    #pragma unroll
    for (int i = 0; i < 8; ++i) {
        int idx = tid + i * 512;
        int row = idx >> 5, ch = idx & 31;
        cp16(sb + SB1 + row * 512 + ((ch ^ (row & 7)) << 4),
             g_Wh + (size_t)(128 + row) * DIM + ch * 8);
    }
    cp_commit();

    // per-thread top-2 for 8 owned token slots (mi*2 + h)
    float v1[8], v2[8];
    int   i1[8], i2[8];
    #pragma unroll
    for (int r = 0; r < 8; ++r) { v1[r] = 3.4e38f; v2[r] = 3.4e38f; i1[r] = 0; i2[r] = 0; }

    for (int nt = 0; nt < 16; ++nt) {
        if (nt < 15) asm volatile("cp.async.wait_group 1;" ::: "memory");
        else         asm volatile("cp.async.wait_group 0;" ::: "memory");
        __syncthreads();
        const uint32_t BB = sb + ((nt & 1) ? SB1 : SB0);

        float c[4][2][4];
        #pragma unroll
        for (int mi = 0; mi < 4; ++mi)
            #pragma unroll
            for (int ni = 0; ni < 2; ++ni)
                #pragma unroll
                for (int e = 0; e < 4; ++e) c[mi][ni][e] = 0.0f;

        #pragma unroll
        for (int ks = 0; ks < 16; ++ks) {
            uint32_t a[4][4];
            #pragma unroll
            for (int mi = 0; mi < 4; ++mi) {
                int row = wm * 64 + mi * 16 + (lane & 15);
                int ch = ks * 2 + (lane >> 4);
                ldm4(sb + SA + row * 512 + ((ch ^ (row & 7)) << 4), a[mi]);
            }
            // B: non-trans ldmatrix, mats 0/1 = codes 0-7 (k-lo,k-hi), 2/3 = codes 8-15
            uint32_t b[4];
            {
                int code = wn * 16 + ((lane & 16) >> 1) + (lane & 7);
                int ch = ks * 2 + ((lane >> 3) & 1);
                ldm4(BB + code * 512 + ((ch ^ (code & 7)) << 4), b);
            }
            #pragma unroll
            for (int mi = 0; mi < 4; ++mi) {
                mma16816(c[mi][0], a[mi], b[0], b[1]);
                mma16816(c[mi][1], a[mi], b[2], b[3]);
            }
        }

        // fold: score = wnorm + acc  (acc = x . (-2w))
        #pragma unroll
        for (int ni = 0; ni < 2; ++ni) {
            int col = nt * 128 + wn * 16 + ni * 8 + (lane & 3) * 2;
            float2 wn2 = *(const float2*)&g_wnorm[col];
            #pragma unroll
            for (int mi = 0; mi < 4; ++mi) {
                #pragma unroll
                for (int h = 0; h < 2; ++h) {
                    int r = mi * 2 + h;
                    float s0 = wn2.x + c[mi][ni][h * 2];
                    float s1 = wn2.y + c[mi][ni][h * 2 + 1];
                    if (s0 < v1[r]) { v2[r] = v1[r]; i2[r] = i1[r]; v1[r] = s0; i1[r] = col; }
                    else if (s0 < v2[r]) { v2[r] = s0; i2[r] = col; }
                    if (s1 < v1[r]) { v2[r] = v1[r]; i2[r] = i1[r]; v1[r] = s1; i1[r] = col + 1; }
                    else if (s1 < v2[r]) { v2[r] = s1; i2[r] = col + 1; }
                }
            }
        }

        __syncthreads();
        if (nt + 2 < 16) {
            const uint32_t NB = sb + ((nt & 1) ? SB1 : SB0);
            #pragma unroll
            for (int i = 0; i < 8; ++i) {
                int idx = tid + i * 512;
                int row = idx >> 5, ch = idx & 31;
                cp16(NB + row * 512 + ((ch ^ (row & 7)) << 4),
                     g_Wh + (size_t)((nt + 2) * 128 + row) * DIM + ch * 8);
            }
            cp_commit();
        }
    }

    // ---- per-token merge: 32 threads x top-2 -> global top-4 (smem, stride 65) ----
    __syncthreads();
    float* cv = (float*)sm;                      // 128 * 65 floats (33280 B)
    int*   ci = (int*)(sm + 33280);              // 128 * 65 ints
    const int slot = wn * 4 + (lane & 3);        // 0..31
    #pragma unroll
    for (int mi = 0; mi < 4; ++mi)
        #pragma unroll
        for (int h = 0; h < 2; ++h) {
            int r = mi * 2 + h;
            int tloc = wm * 64 + mi * 16 + h * 8 + (lane >> 2);
            cv[tloc * 65 + slot * 2]     = v1[r];
            ci[tloc * 65 + slot * 2]     = i1[r];
            cv[tloc * 65 + slot * 2 + 1] = v2[r];
            ci[tloc * 65 + slot * 2 + 1] = i2[r];
        }
    __syncthreads();
    if (tid < 128) {
        float bv0 = 3.4e38f, bv1b = 3.4e38f, bv2b = 3.4e38f, bv3 = 3.4e38f;
        int   bx0 = 0, bx1 = 0, bx2 = 0, bx3 = 0;
        #pragma unroll
        for (int e = 0; e < 64; ++e) {
            float v = cv[tid * 65 + e];
            int   ix = ci[tid * 65 + e];
            if (v < bv3) {
                if (v < bv0) { bv3=bv2b; bx3=bx2; bv2b=bv1b; bx2=bx1; bv1b=bv0; bx1=bx0; bv0=v; bx0=ix; }
                else if (v < bv1b) { bv3=bv2b; bx3=bx2; bv2b=bv1b; bx2=bx1; bv1b=v; bx1=ix; }
                else if (v < bv2b) { bv3=bv2b; bx3=bx2; bv2b=v; bx2=ix; }
                else { bv3=v; bx3=ix; }
            }
        }
        g_cand4[n0 + tid] = make_int4(bx0, bx1, bx2, bx3);
    }
}

// ---------------- exact fp32 rescore of 4 candidates + loss ----------------
__global__ void k_rescore(const float* __restrict__ weight) {
    __shared__ float ls[8];
    const int warp = threadIdx.x >> 5, lane = threadIdx.x & 31;
    float lacc = 0.0f;
    #pragma unroll
    for (int it = 0; it < 4; ++it) {
        int t = (blockIdx.x * 8 + warp) * 4 + it;
        int4 cc = g_cand4[t];
        int cand[4] = {cc.x, cc.y, cc.z, cc.w};
        float xv[8];
        float xn = 0.0f;
        #pragma unroll
        for (int i = 0; i < 8; ++i) {
            xv[i] = g_Xf[(size_t)t * DIM + lane + 32 * i];
            xn += xv[i] * xv[i];
        }
        #pragma unroll
        for (int o = 16; o > 0; o >>= 1) xn += __shfl_xor_sync(0xffffffffu, xn, o);
        float bs = 3.4e38f; int bi = 0x7fffffff;
        #pragma unroll
        for (int j = 0; j < 4; ++j) {
            int k = cand[j];
            float d = 0.0f;
            #pragma unroll
            for (int i = 0; i < 8; ++i)
                d += xv[i] * weight[(size_t)k * DIM + lane + 32 * i];
            #pragma unroll
            for (int o = 16; o > 0; o >>= 1) d += __shfl_xor_sync(0xffffffffu, d, o);
            float s = g_wnorm[k] - 2.0f * d;
            if (s < bs || (s == bs && k < bi)) { bs = s; bi = k; }
        }
        if (lane == 0) {
            g_idx[t] = bi;
            atomicAdd(&g_counts[bi], 1);
            lacc += bs + xn;          // == ||x - w||^2
        }
    }
    if (lane == 0) ls[warp] = lacc;
    __syncthreads();
    if (threadIdx.x == 0) {
        float s = 0.0f;
        #pragma unroll
        for (int w = 0; w < 8; ++w) s += ls[w];
        atomicAdd(&g_loss, s);
    }
}

// ---------------- quantize: q_out + encodings ----------------
__global__ void __launch_bounds__(256)
k_quant(const float* __restrict__ weight, float* __restrict__ out) {
    __shared__ float wrow[64 * 67];
    __shared__ int   idx_s[64];
    const int tid = threadIdx.x, blk = blockIdx.x;
    const int b = blk >> 6, h = blk & 63;
    const int n0 = b * HW + h * 64;
    if (tid < 64) {
        int ix = g_idx[n0 + tid];
        idx_s[tid] = ix;
        out[OFF_ENC + (long long)(n0 + tid) * KCB + ix] = 1.0f;
    }
    __syncthreads();
    const int w = tid & 63, dg = tid >> 6;
    float* qbp = out + OFF_QOUT + (size_t)b * DHW + h * 64 + w;
    for (int c = 0; c < 4; ++c) {
        #pragma unroll
        for (int p = 0; p < 16; ++p) {
            int idx = tid + p * 256;
            int r = idx >> 6, d = idx & 63;
            wrow[r * 67 + d] = weight[(size_t)idx_s[r] * DIM + c * 64 + d];
        }
        __syncthreads();
        #pragma unroll
        for (int s = 0; s < 16; ++s) {
            int dl = dg * 16 + s;
            int d = c * 64 + dl;
            qbp[(size_t)d * HW] = wrow[w * 67 + dl];
        }
        __syncthreads();
    }
}

// ---------------- counting-sort for dw ----------------
__global__ void k_scan() {
    __shared__ int a[1024], bbuf[1024];
    int t = threadIdx.x;
    int c0 = g_counts[2 * t], c1 = g_counts[2 * t + 1];
    a[t] = c0 + c1;
    __syncthreads();
    int* src = a; int* dst = bbuf;
    for (int d = 1; d < 1024; d <<= 1) {
        int v = src[t] + ((t >= d) ? src[t - d] : 0);
        dst[t] = v;
        __syncthreads();
        int* tmp = src; src = dst; dst = tmp;
    }
    int incl = src[t];
    int e = incl - (c0 + c1);
    g_off[2 * t] = e;           g_cur[2 * t] = e;
    g_off[2 * t + 1] = e + c0;  g_cur[2 * t + 1] = e + c0;
}
__global__ void k_scatter() {
    int t = blockIdx.x * 256 + threadIdx.x;
    int ix = g_idx[t];
    int pos = atomicAdd(&g_cur[ix], 1);
    g_perm[pos] = t;
}
// one thread per dim, 4-token unroll (MLP=4)
__global__ void k_dw() {
    const int k = blockIdx.x, d = threadIdx.x;   // 2048 blocks x 256 thr
    const int start = g_off[k], cnt = g_counts[k];
    float a0 = 0.0f, a1 = 0.0f, a2 = 0.0f, a3 = 0.0f;
    int i = 0;
    for (; i + 4 <= cnt; i += 4) {
        int t0 = g_perm[start + i];
        int t1 = g_perm[start + i + 1];
        int t2 = g_perm[start + i + 2];
        int t3 = g_perm[start + i + 3];
        a0 += g_Xf[(size_t)t0 * DIM + d];
        a1 += g_Xf[(size_t)t1 * DIM + d];
        a2 += g_Xf[(size_t)t2 * DIM + d];
        a3 += g_Xf[(size_t)t3 * DIM + d];
    }
    for (; i < cnt; ++i)
        a0 += g_Xf[(size_t)g_perm[start + i] * DIM + d];
    g_dw[(size_t)k * DIM + d] = (a0 + a1) + (a2 + a3);
}

// ---------------- stats ----------------
__global__ void k_stats(const float* __restrict__ ecs, float* __restrict__ out) {
    __shared__ float sn[1024];
    __shared__ float sh[1024];
    int t = threadIdx.x;
    float c0 = (float)g_counts[t];
    float c1 = (float)g_counts[t + 1024];
    float cs0 = ecs[t] * DECAYF + OMD * c0;
    float cs1 = ecs[t + 1024] * DECAYF + OMD * c1;
    float p0 = c0 / 65536.0f, p1 = c1 / 65536.0f;
    sn[t] = cs0 + cs1;
    sh[t] = p0 * logf(p0 + 1e-10f) + p1 * logf(p1 + 1e-10f);
    __syncthreads();
    #pragma unroll
    for (int st = 512; st > 0; st >>= 1) {
        if (t < st) { sn[t] += sn[t + st]; sh[t] += sh[t + st]; }
        __syncthreads();
    }
    float n = sn[0];
    float denom = n + (float)KCB * EPSF;
    out[OFF_CS + t]        = (cs0 + EPSF) / denom * n;
    out[OFF_CS + t + 1024] = (cs1 + EPSF) / denom * n;
    if (t == 0) {
        out[OFF_PERP] = expf(-sh[0]);
        out[OFF_LOSS] = 0.25f * g_loss / 16777216.0f;
    }
}

// ---------------- EMA update ----------------
__global__ void k_ema(const float* __restrict__ emaw, float* __restrict__ out) {
    int i = blockIdx.x * 256 + threadIdx.x;
    float e = emaw[i] * DECAYF + OMD * g_dw[i];
    out[OFF_EMAW + i] = e;
    out[OFF_W + i]    = e / out[OFF_CS + (i >> 8)];
}

// ---------------- launch ----------------
extern "C" void kernel_launch(void* const* d_in, const int* in_sizes, int n_in,
                              void* d_out, int out_size) {
    const float* z    = (const float*)d_in[0];
    const float* wgt  = (const float*)d_in[1];
    const float* ecs  = (const float*)d_in[2];
    const float* emaw = (const float*)d_in[3];
    float* out = (float*)d_out;

    cudaFuncSetAttribute(k_gemm,   cudaFuncAttributeMaxDynamicSharedMemorySize, SMT);
    cudaFuncSetAttribute(k_prep_x, cudaFuncAttributeMaxDynamicSharedMemorySize, 64 * 260 * 4);

    cudaMemsetAsync(out + OFF_ENC, 0, (size_t)NTOT * KCB * sizeof(float), 0);

    k_init   <<<8, 256>>>();
    k_prep_w <<<256, 256>>>(wgt);
    k_prep_x <<<1024, 256, 64 * 260 * 4>>>(z);
    k_gemm   <<<512, 512, SMT>>>();
    k_rescore<<<2048, 256>>>(wgt);
    k_quant  <<<1024, 256>>>(wgt, out);
    k_scan   <<<1, 1024>>>();
    k_scatter<<<256, 256>>>();
    k_dw     <<<2048, 256>>>();
    k_stats  <<<1, 1024>>>(ecs, out);
    k_ema    <<<2048, 256>>>(emaw, out);
}

// round 8
// speedup vs baseline: 2.4925x; 1.0214x over previous
#include <cuda_runtime.h>
#include <cuda_fp16.h>
#include <math.h>
#include <stdint.h>

// ---------------- problem constants ----------------
#define NTOT   65536
#define KCB    2048
#define DIM    256
#define HW     4096
#define DHW    1048576

#define OFF_LOSS 0LL
#define OFF_QOUT 1LL
#define OFF_PERP 16777217LL
#define OFF_ENC  16777218LL
#define OFF_CS   150994946LL
#define OFF_EMAW 150996994LL
#define OFF_W    151521282LL

static const float DECAYF = 0.99f;
static const float OMD    = 0.01f;
static const float EPSF   = 1e-5f;

// ---------------- device scratch ----------------
__device__ __half g_Xh[NTOT * DIM];     // token-major fp16 x      (32MB)
__device__ __half g_Wh[KCB * DIM];      // code-major fp16 (-2w)   (1MB)
__device__ float  g_Xf[NTOT * DIM];     // token-major fp32 x      (64MB)
__device__ float  g_wnorm[KCB];
__device__ int    g_counts[KCB];
__device__ int    g_off[KCB];
__device__ int    g_cur[KCB];
__device__ int    g_perm[NTOT];
__device__ int    g_idx[NTOT];
__device__ int4   g_cand4[NTOT];        // 4 exact-rescore candidates per token (1MB)
__device__ float  g_dw[KCB * DIM];
__device__ float  g_loss;

// ---------------- helpers ----------------
__device__ __forceinline__ uint32_t smem_u32(const void* p) {
    uint32_t a;
    asm("{ .reg .u64 t; cvta.to.shared.u64 t, %1; cvt.u32.u64 %0, t; }" : "=r"(a) : "l"(p));
    return a;
}
__device__ __forceinline__ void cp16(uint32_t dst, const void* src) {
    asm volatile("cp.async.cg.shared.global [%0], [%1], 16;" :: "r"(dst), "l"(src) : "memory");
}
__device__ __forceinline__ void cp_commit() { asm volatile("cp.async.commit_group;" ::: "memory"); }

__device__ __forceinline__ void ldm4(uint32_t a, uint32_t r[4]) {
    asm volatile("ldmatrix.sync.aligned.m8n8.x4.shared.b16 {%0,%1,%2,%3}, [%4];"
                 : "=r"(r[0]), "=r"(r[1]), "=r"(r[2]), "=r"(r[3]) : "r"(a));
}
// fp16-accumulate HMMA (2x rate vs f32 accum)
__device__ __forceinline__ void mma16816h(uint32_t c[2], const uint32_t a[4],
                                          uint32_t b0, uint32_t b1) {
    asm volatile("mma.sync.aligned.m16n8k16.row.col.f16.f16.f16.f16 "
                 "{%0,%1},{%2,%3,%4,%5},{%6,%7},{%0,%1};"
                 : "+r"(c[0]), "+r"(c[1])
                 : "r"(a[0]), "r"(a[1]), "r"(a[2]), "r"(a[3]), "r"(b0), "r"(b1));
}

// ---------------- codebook prep: fp16(-2w) + norms + init ----------------
__global__ void k_prep_w(const float* __restrict__ weight) {
    int warp = threadIdx.x >> 5, lane = threadIdx.x & 31;
    int k = blockIdx.x * 8 + warp;               // 256 blocks
    float s = 0.0f;
    #pragma unroll
    for (int i = 0; i < 8; ++i) {
        int d = lane + i * 32;
        float v = weight[(size_t)k * DIM + d];
        g_Wh[(size_t)k * DIM + d] = __float2half(-2.0f * v);
        s += v * v;
    }
    #pragma unroll
    for (int o = 16; o > 0; o >>= 1) s += __shfl_down_sync(0xffffffffu, s, o);
    if (lane == 0) {
        g_wnorm[k] = s;
        g_counts[k] = 0;
        if (k == 0) g_loss = 0.0f;
    }
}

// ---------------- x prep: transpose to token-major fp32 + fp16 ----------------
__global__ void k_prep_x(const float* __restrict__ z) {
    extern __shared__ float xs[];             // 64*260
    const int tid = threadIdx.x;
    const int n0 = blockIdx.x * 64;
    const int b = n0 >> 12, sp0 = n0 & 4095;
    const float* zb = z + (size_t)b * DHW + sp0;
    #pragma unroll
    for (int p = 0; p < 16; ++p) {
        int lin = tid + p * 256;
        int q = lin & 63, dq4 = lin >> 6;
        float4 v;
        v.x = zb[(dq4 * 4 + 0) * HW + q];
        v.y = zb[(dq4 * 4 + 1) * HW + q];
        v.z = zb[(dq4 * 4 + 2) * HW + q];
        v.w = zb[(dq4 * 4 + 3) * HW + q];
        *(float4*)(xs + q * 260 + dq4 * 4) = v;
    }
    __syncthreads();
    #pragma unroll
    for (int p = 0; p < 64; ++p) {
        int lin = tid + p * 256;
        int q = lin >> 8, d = lin & 255;
        float v = xs[q * 260 + d];
        size_t t = (size_t)(n0 + q);
        g_Xh[t * DIM + d] = __float2half(v);
        g_Xf[t * DIM + d] = v;
    }
}

// ---------------- HMMA argmin GEMM (fp16 accum) + enc zero-fill ----------------
// 512 CTAs x 512 thr (16 warps: 2m x 8n). CTA = 128 tokens x 2048 codes, K=256.
// A (128x256 fp16, 64KB) resident; B (128x256, 64KB) double-buffered cp.async.
// Warp tile 64 tokens x 16 codes. Also zeroes its 1MB slice of encodings via
// float2 streaming stores (8B-aligned; OFF_ENC is not 16B-aligned).
#define SA  0
#define SB0 65536
#define SB1 131072
#define SMT 196608

__global__ void __launch_bounds__(512, 1)
k_gemm(float* __restrict__ out) {
    extern __shared__ char sm[];
    const uint32_t sb = smem_u32(sm);
    const int tid = threadIdx.x;
    const int lane = tid & 31, warp = tid >> 5;
    const int wm = warp & 1, wn = warp >> 1;      // wm: token half, wn: 0..7
    const int n0 = blockIdx.x * 128;
    float2* enc2 = (float2*)(out + OFF_ENC) + (size_t)blockIdx.x * 131072;

    // A tile (grouped with B0)
    #pragma unroll
    for (int i = 0; i < 8; ++i) {
        int idx = tid + i * 512;                 // 4096 chunks
        int row = idx >> 5, ch = idx & 31;
        cp16(sb + SA + row * 512 + ((ch ^ (row & 7)) << 4),
             g_Xh + (size_t)(n0 + row) * DIM + ch * 8);
    }
    // B tile 0
    #pragma unroll
    for (int i = 0; i < 8; ++i) {
        int idx = tid + i * 512;
        int row = idx >> 5, ch = idx & 31;
        cp16(sb + SB0 + row * 512 + ((ch ^ (row & 7)) << 4),
             g_Wh + (size_t)row * DIM + ch * 8);
    }
    cp_commit();
    // B tile 1
    #pragma unroll
    for (int i = 0; i < 8; ++i) {
        int idx = tid + i * 512;
        int row = idx >> 5, ch = idx & 31;
        cp16(sb + SB1 + row * 512 + ((ch ^ (row & 7)) << 4),
             g_Wh + (size_t)(128 + row) * DIM + ch * 8);
    }
    cp_commit();

    // per-thread top-2 for 8 owned token slots (mi*2 + h)
    float v1[8], v2[8];
    int   i1[8], i2[8];
    #pragma unroll
    for (int r = 0; r < 8; ++r) { v1[r] = 3.4e38f; v2[r] = 3.4e38f; i1[r] = 0; i2[r] = 0; }

    const float2 zz = make_float2(0.f, 0.f);

    for (int nt = 0; nt < 16; ++nt) {
        if (nt < 15) asm volatile("cp.async.wait_group 1;" ::: "memory");
        else         asm volatile("cp.async.wait_group 0;" ::: "memory");
        __syncthreads();
        const uint32_t BB = sb + ((nt & 1) ? SB1 : SB0);

        uint32_t c[4][2][2];
        #pragma unroll
        for (int mi = 0; mi < 4; ++mi)
            #pragma unroll
            for (int ni = 0; ni < 2; ++ni) { c[mi][ni][0] = 0u; c[mi][ni][1] = 0u; }

        #pragma unroll
        for (int ks = 0; ks < 16; ++ks) {
            uint32_t a[4][4];
            #pragma unroll
            for (int mi = 0; mi < 4; ++mi) {
                int row = wm * 64 + mi * 16 + (lane & 15);
                int ch = ks * 2 + (lane >> 4);
                ldm4(sb + SA + row * 512 + ((ch ^ (row & 7)) << 4), a[mi]);
            }
            // B: non-trans ldmatrix, mats 0/1 = codes 0-7 (k-lo,k-hi), 2/3 = codes 8-15
            uint32_t b[4];
            {
                int code = wn * 16 + ((lane & 16) >> 1) + (lane & 7);
                int ch = ks * 2 + ((lane >> 3) & 1);
                ldm4(BB + code * 512 + ((ch ^ (code & 7)) << 4), b);
            }
            #pragma unroll
            for (int mi = 0; mi < 4; ++mi) {
                mma16816h(c[mi][0], a[mi], b[0], b[1]);
                mma16816h(c[mi][1], a[mi], b[2], b[3]);
            }
        }

        // zero 16 float2 chunks of this CTA's encodings slice (streaming, 8B-aligned)
        #pragma unroll
        for (int j = 0; j < 16; ++j)
            __stcs(enc2 + (size_t)(nt * 16 + j) * 512 + tid, zz);

        // fold: score = wnorm + acc  (acc = x . (-2w), fp16 pair)
        #pragma unroll
        for (int ni = 0; ni < 2; ++ni) {
            int col = nt * 128 + wn * 16 + ni * 8 + (lane & 3) * 2;
            float2 wn2 = *(const float2*)&g_wnorm[col];
            #pragma unroll
            for (int mi = 0; mi < 4; ++mi) {
                #pragma unroll
                for (int h = 0; h < 2; ++h) {
                    int r = mi * 2 + h;
                    float2 cf = __half22float2(*(__half2*)&c[mi][ni][h]);
                    float s0 = wn2.x + cf.x;
                    float s1 = wn2.y + cf.y;
                    if (s0 < v1[r]) { v2[r] = v1[r]; i2[r] = i1[r]; v1[r] = s0; i1[r] = col; }
                    else if (s0 < v2[r]) { v2[r] = s0; i2[r] = col; }
                    if (s1 < v1[r]) { v2[r] = v1[r]; i2[r] = i1[r]; v1[r] = s1; i1[r] = col + 1; }
                    else if (s1 < v2[r]) { v2[r] = s1; i2[r] = col + 1; }
                }
            }
        }

        __syncthreads();
        if (nt + 2 < 16) {
            const uint32_t NB = sb + ((nt & 1) ? SB1 : SB0);
            #pragma unroll
            for (int i = 0; i < 8; ++i) {
                int idx = tid + i * 512;
                int row = idx >> 5, ch = idx & 31;
                cp16(NB + row * 512 + ((ch ^ (row & 7)) << 4),
                     g_Wh + (size_t)((nt + 2) * 128 + row) * DIM + ch * 8);
            }
            cp_commit();
        }
    }

    // ---- per-token merge: 32 threads x top-2 -> global top-4 (smem, stride 65) ----
    __syncthreads();
    float* cv = (float*)sm;                      // 128 * 65 floats (33280 B)
    int*   ci = (int*)(sm + 33280);              // 128 * 65 ints
    const int slot = wn * 4 + (lane & 3);        // 0..31
    #pragma unroll
    for (int mi = 0; mi < 4; ++mi)
        #pragma unroll
        for (int h = 0; h < 2; ++h) {
            int r = mi * 2 + h;
            int tloc = wm * 64 + mi * 16 + h * 8 + (lane >> 2);
            cv[tloc * 65 + slot * 2]     = v1[r];
            ci[tloc * 65 + slot * 2]     = i1[r];
            cv[tloc * 65 + slot * 2 + 1] = v2[r];
            ci[tloc * 65 + slot * 2 + 1] = i2[r];
        }
    __syncthreads();
    if (tid < 128) {
        float bv0 = 3.4e38f, bv1b = 3.4e38f, bv2b = 3.4e38f, bv3 = 3.4e38f;
        int   bx0 = 0, bx1 = 0, bx2 = 0, bx3 = 0;
        #pragma unroll
        for (int e = 0; e < 64; ++e) {
            float v = cv[tid * 65 + e];
            int   ix = ci[tid * 65 + e];
            if (v < bv3) {
                if (v < bv0) { bv3=bv2b; bx3=bx2; bv2b=bv1b; bx2=bx1; bv1b=bv0; bx1=bx0; bv0=v; bx0=ix; }
                else if (v < bv1b) { bv3=bv2b; bx3=bx2; bv2b=bv1b; bx2=bx1; bv1b=v; bx1=ix; }
                else if (v < bv2b) { bv3=bv2b; bx3=bx2; bv2b=v; bx2=ix; }
                else { bv3=v; bx3=ix; }
            }
        }
        g_cand4[n0 + tid] = make_int4(bx0, bx1, bx2, bx3);
    }
}

// ---------------- exact fp32 rescore of 4 candidates + loss ----------------
__global__ void k_rescore(const float* __restrict__ weight) {
    __shared__ float ls[8];
    const int warp = threadIdx.x >> 5, lane = threadIdx.x & 31;
    float lacc = 0.0f;
    #pragma unroll
    for (int it = 0; it < 4; ++it) {
        int t = (blockIdx.x * 8 + warp) * 4 + it;
        int4 cc = g_cand4[t];
        int cand[4] = {cc.x, cc.y, cc.z, cc.w};
        float xv[8];
        float xn = 0.0f;
        #pragma unroll
        for (int i = 0; i < 8; ++i) {
            xv[i] = g_Xf[(size_t)t * DIM + lane + 32 * i];
            xn += xv[i] * xv[i];
        }
        #pragma unroll
        for (int o = 16; o > 0; o >>= 1) xn += __shfl_xor_sync(0xffffffffu, xn, o);
        float bs = 3.4e38f; int bi = 0x7fffffff;
        #pragma unroll
        for (int j = 0; j < 4; ++j) {
            int k = cand[j];
            float d = 0.0f;
            #pragma unroll
            for (int i = 0; i < 8; ++i)
                d += xv[i] * weight[(size_t)k * DIM + lane + 32 * i];
            #pragma unroll
            for (int o = 16; o > 0; o >>= 1) d += __shfl_xor_sync(0xffffffffu, d, o);
            float s = g_wnorm[k] - 2.0f * d;
            if (s < bs || (s == bs && k < bi)) { bs = s; bi = k; }
        }
        if (lane == 0) {
            g_idx[t] = bi;
            atomicAdd(&g_counts[bi], 1);
            lacc += bs + xn;          // == ||x - w||^2
        }
    }
    if (lane == 0) ls[warp] = lacc;
    __syncthreads();
    if (threadIdx.x == 0) {
        float s = 0.0f;
        #pragma unroll
        for (int w = 0; w < 8; ++w) s += ls[w];
        atomicAdd(&g_loss, s);
    }
}

// ---------------- quantize: q_out + encodings ----------------
__global__ void __launch_bounds__(256)
k_quant(const float* __restrict__ weight, float* __restrict__ out) {
    __shared__ float wrow[64 * 67];
    __shared__ int   idx_s[64];
    const int tid = threadIdx.x, blk = blockIdx.x;
    const int b = blk >> 6, h = blk & 63;
    const int n0 = b * HW + h * 64;
    if (tid < 64) {
        int ix = g_idx[n0 + tid];
        idx_s[tid] = ix;
        out[OFF_ENC + (long long)(n0 + tid) * KCB + ix] = 1.0f;
    }
    __syncthreads();
    const int w = tid & 63, dg = tid >> 6;
    float* qbp = out + OFF_QOUT + (size_t)b * DHW + h * 64 + w;
    for (int c = 0; c < 4; ++c) {
        #pragma unroll
        for (int p = 0; p < 16; ++p) {
            int idx = tid + p * 256;
            int r = idx >> 6, d = idx & 63;
            wrow[r * 67 + d] = weight[(size_t)idx_s[r] * DIM + c * 64 + d];
        }
        __syncthreads();
        #pragma unroll
        for (int s = 0; s < 16; ++s) {
            int dl = dg * 16 + s;
            int d = c * 64 + dl;
            qbp[(size_t)d * HW] = wrow[w * 67 + dl];
        }
        __syncthreads();
    }
}

// ---------------- counting-sort for dw ----------------
__global__ void k_scan() {
    __shared__ int a[1024], bbuf[1024];
    int t = threadIdx.x;
    int c0 = g_counts[2 * t], c1 = g_counts[2 * t + 1];
    a[t] = c0 + c1;
    __syncthreads();
    int* src = a; int* dst = bbuf;
    for (int d = 1; d < 1024; d <<= 1) {
        int v = src[t] + ((t >= d) ? src[t - d] : 0);
        dst[t] = v;
        __syncthreads();
        int* tmp = src; src = dst; dst = tmp;
    }
    int incl = src[t];
    int e = incl - (c0 + c1);
    g_off[2 * t] = e;           g_cur[2 * t] = e;
    g_off[2 * t + 1] = e + c0;  g_cur[2 * t + 1] = e + c0;
}
__global__ void k_scatter() {
    int t = blockIdx.x * 256 + threadIdx.x;
    int ix = g_idx[t];
    int pos = atomicAdd(&g_cur[ix], 1);
    g_perm[pos] = t;
}
// one thread per dim, 4-token unroll (MLP=4)
__global__ void k_dw() {
    const int k = blockIdx.x, d = threadIdx.x;   // 2048 blocks x 256 thr
    const int start = g_off[k], cnt = g_counts[k];
    float a0 = 0.0f, a1 = 0.0f, a2 = 0.0f, a3 = 0.0f;
    int i = 0;
    for (; i + 4 <= cnt; i += 4) {
        int t0 = g_perm[start + i];
        int t1 = g_perm[start + i + 1];
        int t2 = g_perm[start + i + 2];
        int t3 = g_perm[start + i + 3];
        a0 += g_Xf[(size_t)t0 * DIM + d];
        a1 += g_Xf[(size_t)t1 * DIM + d];
        a2 += g_Xf[(size_t)t2 * DIM + d];
        a3 += g_Xf[(size_t)t3 * DIM + d];
    }
    for (; i < cnt; ++i)
        a0 += g_Xf[(size_t)g_perm[start + i] * DIM + d];
    g_dw[(size_t)k * DIM + d] = (a0 + a1) + (a2 + a3);
}

// ---------------- stats ----------------
__global__ void k_stats(const float* __restrict__ ecs, float* __restrict__ out) {
    __shared__ float sn[1024];
    __shared__ float sh[1024];
    int t = threadIdx.x;
    float c0 = (float)g_counts[t];
    float c1 = (float)g_counts[t + 1024];
    float cs0 = ecs[t] * DECAYF + OMD * c0;
    float cs1 = ecs[t + 1024] * DECAYF + OMD * c1;
    float p0 = c0 / 65536.0f, p1 = c1 / 65536.0f;
    sn[t] = cs0 + cs1;
    sh[t] = p0 * logf(p0 + 1e-10f) + p1 * logf(p1 + 1e-10f);
    __syncthreads();
    #pragma unroll
    for (int st = 512; st > 0; st >>= 1) {
        if (t < st) { sn[t] += sn[t + st]; sh[t] += sh[t + st]; }
        __syncthreads();
    }
    float n = sn[0];
    float denom = n + (float)KCB * EPSF;
    out[OFF_CS + t]        = (cs0 + EPSF) / denom * n;
    out[OFF_CS + t + 1024] = (cs1 + EPSF) / denom * n;
    if (t == 0) {
        out[OFF_PERP] = expf(-sh[0]);
        out[OFF_LOSS] = 0.25f * g_loss / 16777216.0f;
    }
}

// ---------------- EMA update ----------------
__global__ void k_ema(const float* __restrict__ emaw, float* __restrict__ out) {
    int i = blockIdx.x * 256 + threadIdx.x;
    float e = emaw[i] * DECAYF + OMD * g_dw[i];
    out[OFF_EMAW + i] = e;
    out[OFF_W + i]    = e / out[OFF_CS + (i >> 8)];
}

// ---------------- launch ----------------
extern "C" void kernel_launch(void* const* d_in, const int* in_sizes, int n_in,
                              void* d_out, int out_size) {
    const float* z    = (const float*)d_in[0];
    const float* wgt  = (const float*)d_in[1];
    const float* ecs  = (const float*)d_in[2];
    const float* emaw = (const float*)d_in[3];
    float* out = (float*)d_out;

    cudaFuncSetAttribute(k_gemm,   cudaFuncAttributeMaxDynamicSharedMemorySize, SMT);
    cudaFuncSetAttribute(k_prep_x, cudaFuncAttributeMaxDynamicSharedMemorySize, 64 * 260 * 4);

    k_prep_w <<<256, 256>>>(wgt);
    k_prep_x <<<1024, 256, 64 * 260 * 4>>>(z);
    k_gemm   <<<512, 512, SMT>>>(out);
    k_rescore<<<2048, 256>>>(wgt);
    k_quant  <<<1024, 256>>>(wgt, out);
    k_scan   <<<1, 1024>>>();
    k_scatter<<<256, 256>>>();
    k_dw     <<<2048, 256>>>();
    k_stats  <<<1, 1024>>>(ecs, out);
    k_ema    <<<2048, 256>>>(emaw, out);
}

// round 9
// speedup vs baseline: 4.2123x; 1.6900x over previous
#include <cuda_runtime.h>
#include <cuda_fp16.h>
#include <math.h>
#include <stdint.h>

// ---------------- problem constants ----------------
#define NTOT   65536
#define KCB    2048
#define DIM    256
#define HW     4096
#define DHW    1048576

#define OFF_LOSS 0LL
#define OFF_QOUT 1LL
#define OFF_PERP 16777217LL
#define OFF_ENC  16777218LL
#define OFF_CS   150994946LL
#define OFF_EMAW 150996994LL
#define OFF_W    151521282LL

static const float DECAYF = 0.99f;
static const float OMD    = 0.01f;
static const float EPSF   = 1e-5f;

// ---------------- device scratch ----------------
__device__ __half g_Xh[NTOT * DIM];     // token-major fp16 x      (32MB)
__device__ __half g_Wh[KCB * DIM];      // code-major fp16 (-2w)   (1MB)
__device__ float  g_Xf[NTOT * DIM];     // token-major fp32 x      (64MB)
__device__ float  g_wnorm[KCB];
__device__ int    g_counts[KCB];
__device__ int    g_idx[NTOT];
__device__ int4   g_cand4[NTOT];        // 4 exact-rescore candidates per token (1MB)
__device__ float  g_dw[KCB * DIM];
__device__ float  g_loss;

// ---------------- helpers ----------------
__device__ __forceinline__ uint32_t smem_u32(const void* p) {
    uint32_t a;
    asm("{ .reg .u64 t; cvta.to.shared.u64 t, %1; cvt.u32.u64 %0, t; }" : "=r"(a) : "l"(p));
    return a;
}
__device__ __forceinline__ void cp16(uint32_t dst, const void* src) {
    asm volatile("cp.async.cg.shared.global [%0], [%1], 16;" :: "r"(dst), "l"(src) : "memory");
}
__device__ __forceinline__ void cp_commit() { asm volatile("cp.async.commit_group;" ::: "memory"); }

__device__ __forceinline__ void ldm4(uint32_t a, uint32_t r[4]) {
    asm volatile("ldmatrix.sync.aligned.m8n8.x4.shared.b16 {%0,%1,%2,%3}, [%4];"
                 : "=r"(r[0]), "=r"(r[1]), "=r"(r[2]), "=r"(r[3]) : "r"(a));
}
// fp16-accumulate HMMA
__device__ __forceinline__ void mma16816h(uint32_t c[2], const uint32_t a[4],
                                          uint32_t b0, uint32_t b1) {
    asm volatile("mma.sync.aligned.m16n8k16.row.col.f16.f16.f16.f16 "
                 "{%0,%1},{%2,%3,%4,%5},{%6,%7},{%0,%1};"
                 : "+r"(c[0]), "+r"(c[1])
                 : "r"(a[0]), "r"(a[1]), "r"(a[2]), "r"(a[3]), "r"(b0), "r"(b1));
}

// ---------------- codebook prep: fp16(-2w) + norms + init ----------------
__global__ void k_prep_w(const float* __restrict__ weight) {
    int warp = threadIdx.x >> 5, lane = threadIdx.x & 31;
    int k = blockIdx.x * 8 + warp;               // 256 blocks
    float s = 0.0f;
    #pragma unroll
    for (int i = 0; i < 8; ++i) {
        int d = lane + i * 32;
        float v = weight[(size_t)k * DIM + d];
        g_Wh[(size_t)k * DIM + d] = __float2half(-2.0f * v);
        s += v * v;
    }
    #pragma unroll
    for (int o = 16; o > 0; o >>= 1) s += __shfl_down_sync(0xffffffffu, s, o);
    if (lane == 0) {
        g_wnorm[k] = s;
        g_counts[k] = 0;
        if (k == 0) g_loss = 0.0f;
    }
}

// ---------------- x prep: transpose to token-major fp32 + fp16; zero dw ----------------
__global__ void k_prep_x(const float* __restrict__ z) {
    extern __shared__ float xs[];             // 64*260
    const int tid = threadIdx.x;
    // zero g_dw (1024 blocks x 512 elems)
    g_dw[(size_t)blockIdx.x * 512 + tid] = 0.0f;
    g_dw[(size_t)blockIdx.x * 512 + 256 + tid] = 0.0f;

    const int n0 = blockIdx.x * 64;
    const int b = n0 >> 12, sp0 = n0 & 4095;
    const float* zb = z + (size_t)b * DHW + sp0;
    #pragma unroll
    for (int p = 0; p < 16; ++p) {
        int lin = tid + p * 256;
        int q = lin & 63, dq4 = lin >> 6;
        float4 v;
        v.x = zb[(dq4 * 4 + 0) * HW + q];
        v.y = zb[(dq4 * 4 + 1) * HW + q];
        v.z = zb[(dq4 * 4 + 2) * HW + q];
        v.w = zb[(dq4 * 4 + 3) * HW + q];
        *(float4*)(xs + q * 260 + dq4 * 4) = v;
    }
    __syncthreads();
    #pragma unroll
    for (int p = 0; p < 64; ++p) {
        int lin = tid + p * 256;
        int q = lin >> 8, d = lin & 255;
        float v = xs[q * 260 + d];
        size_t t = (size_t)(n0 + q);
        g_Xh[t * DIM + d] = __float2half(v);
        g_Xf[t * DIM + d] = v;
    }
}

// ---------------- HMMA argmin GEMM (fp16 accum) + enc zero-fill ----------------
// 512 CTAs x 512 thr (16 warps: 4m x 4n, warp tile 32x32). CTA = 128 tokens x
// 2048 codes, K=256. A resident (64KB); B double-buffered (2x64KB) cp.async.
// Per-thread top-3; 48 candidates per token merged to top-4.
#define SA  0
#define SB0 65536
#define SB1 131072
#define SMT 196608

__global__ void __launch_bounds__(512, 1)
k_gemm(float* __restrict__ out) {
    extern __shared__ char sm[];
    const uint32_t sb = smem_u32(sm);
    const int tid = threadIdx.x;
    const int lane = tid & 31, warp = tid >> 5;
    const int wm = warp & 3, wn = warp >> 2;      // 4m x 4n
    const int n0 = blockIdx.x * 128;
    float2* enc2 = (float2*)(out + OFF_ENC) + (size_t)blockIdx.x * 131072;

    // A tile (grouped with B0)
    #pragma unroll
    for (int i = 0; i < 8; ++i) {
        int idx = tid + i * 512;                 // 4096 chunks
        int row = idx >> 5, ch = idx & 31;
        cp16(sb + SA + row * 512 + ((ch ^ (row & 7)) << 4),
             g_Xh + (size_t)(n0 + row) * DIM + ch * 8);
    }
    // B tile 0
    #pragma unroll
    for (int i = 0; i < 8; ++i) {
        int idx = tid + i * 512;
        int row = idx >> 5, ch = idx & 31;
        cp16(sb + SB0 + row * 512 + ((ch ^ (row & 7)) << 4),
             g_Wh + (size_t)row * DIM + ch * 8);
    }
    cp_commit();
    // B tile 1
    #pragma unroll
    for (int i = 0; i < 8; ++i) {
        int idx = tid + i * 512;
        int row = idx >> 5, ch = idx & 31;
        cp16(sb + SB1 + row * 512 + ((ch ^ (row & 7)) << 4),
             g_Wh + (size_t)(128 + row) * DIM + ch * 8);
    }
    cp_commit();

    // per-thread top-3 for 4 owned token slots (r = mi*2 + h)
    float v1[4], v2[4], v3[4];
    int   i1[4], i2[4], i3[4];
    #pragma unroll
    for (int r = 0; r < 4; ++r) {
        v1[r] = 3.4e38f; v2[r] = 3.4e38f; v3[r] = 3.4e38f;
        i1[r] = 0; i2[r] = 0; i3[r] = 0;
    }

    const float2 zz = make_float2(0.f, 0.f);

    for (int nt = 0; nt < 16; ++nt) {
        if (nt < 15) asm volatile("cp.async.wait_group 1;" ::: "memory");
        else         asm volatile("cp.async.wait_group 0;" ::: "memory");
        __syncthreads();
        const uint32_t BB = sb + ((nt & 1) ? SB1 : SB0);

        uint32_t c[2][4][2];
        #pragma unroll
        for (int mi = 0; mi < 2; ++mi)
            #pragma unroll
            for (int ni = 0; ni < 4; ++ni) { c[mi][ni][0] = 0u; c[mi][ni][1] = 0u; }

        #pragma unroll
        for (int ks = 0; ks < 16; ++ks) {
            uint32_t a[2][4];
            #pragma unroll
            for (int mi = 0; mi < 2; ++mi) {
                int row = wm * 32 + mi * 16 + (lane & 15);
                int ch = ks * 2 + (lane >> 4);
                ldm4(sb + SA + row * 512 + ((ch ^ (row & 7)) << 4), a[mi]);
            }
            // B: non-trans ldmatrix on code-major smem; g covers 16 codes each.
            uint32_t b0[4], b1[4];
            {
                int code = wn * 32 + ((lane & 16) >> 1) + (lane & 7);
                int ch = ks * 2 + ((lane >> 3) & 1);
                ldm4(BB + code * 512 + ((ch ^ (code & 7)) << 4), b0);
                code += 16;
                ldm4(BB + code * 512 + ((ch ^ (code & 7)) << 4), b1);
            }
            #pragma unroll
            for (int mi = 0; mi < 2; ++mi) {
                mma16816h(c[mi][0], a[mi], b0[0], b0[1]);
                mma16816h(c[mi][1], a[mi], b0[2], b0[3]);
                mma16816h(c[mi][2], a[mi], b1[0], b1[1]);
                mma16816h(c[mi][3], a[mi], b1[2], b1[3]);
            }
        }

        // zero 16 float2 chunks of this CTA's encodings slice (streaming, 8B-aligned)
        #pragma unroll
        for (int j = 0; j < 16; ++j)
            __stcs(enc2 + (size_t)(nt * 16 + j) * 512 + tid, zz);

        // fold: score = wnorm + acc  (acc = x . (-2w), fp16 pair); top-3 insert
        #pragma unroll
        for (int ni = 0; ni < 4; ++ni) {
            int col = nt * 128 + wn * 32 + ni * 8 + (lane & 3) * 2;
            float2 wn2 = *(const float2*)&g_wnorm[col];
            #pragma unroll
            for (int mi = 0; mi < 2; ++mi) {
                #pragma unroll
                for (int h = 0; h < 2; ++h) {
                    int r = mi * 2 + h;
                    float2 cf = __half22float2(*(__half2*)&c[mi][ni][h]);
                    float s0 = wn2.x + cf.x;
                    float s1 = wn2.y + cf.y;
                    if (s0 < v3[r]) {
                        if (s0 < v1[r]) { v3[r]=v2[r]; i3[r]=i2[r]; v2[r]=v1[r]; i2[r]=i1[r]; v1[r]=s0; i1[r]=col; }
                        else if (s0 < v2[r]) { v3[r]=v2[r]; i3[r]=i2[r]; v2[r]=s0; i2[r]=col; }
                        else { v3[r]=s0; i3[r]=col; }
                    }
                    if (s1 < v3[r]) {
                        if (s1 < v1[r]) { v3[r]=v2[r]; i3[r]=i2[r]; v2[r]=v1[r]; i2[r]=i1[r]; v1[r]=s1; i1[r]=col+1; }
                        else if (s1 < v2[r]) { v3[r]=v2[r]; i3[r]=i2[r]; v2[r]=s1; i2[r]=col+1; }
                        else { v3[r]=s1; i3[r]=col+1; }
                    }
                }
            }
        }

        __syncthreads();
        if (nt + 2 < 16) {
            const uint32_t NB = sb + ((nt & 1) ? SB1 : SB0);
            #pragma unroll
            for (int i = 0; i < 8; ++i) {
                int idx = tid + i * 512;
                int row = idx >> 5, ch = idx & 31;
                cp16(NB + row * 512 + ((ch ^ (row & 7)) << 4),
                     g_Wh + (size_t)((nt + 2) * 128 + row) * DIM + ch * 8);
            }
            cp_commit();
        }
    }

    // ---- per-token merge: 16 threads x top-3 -> global top-4 (smem, stride 49) ----
    __syncthreads();
    float* cv = (float*)sm;                      // 128 * 49 floats (25088 B)
    int*   ci = (int*)(sm + 25088);              // 128 * 49 ints
    const int slot = wn * 4 + (lane & 3);        // 0..15
    #pragma unroll
    for (int mi = 0; mi < 2; ++mi)
        #pragma unroll
        for (int h = 0; h < 2; ++h) {
            int r = mi * 2 + h;
            int tloc = wm * 32 + mi * 16 + h * 8 + (lane >> 2);
            cv[tloc * 49 + slot * 3 + 0] = v1[r];  ci[tloc * 49 + slot * 3 + 0] = i1[r];
            cv[tloc * 49 + slot * 3 + 1] = v2[r];  ci[tloc * 49 + slot * 3 + 1] = i2[r];
            cv[tloc * 49 + slot * 3 + 2] = v3[r];  ci[tloc * 49 + slot * 3 + 2] = i3[r];
        }
    __syncthreads();
    if (tid < 128) {
        float bv0 = 3.4e38f, bv1b = 3.4e38f, bv2b = 3.4e38f, bv3 = 3.4e38f;
        int   bx0 = 0, bx1 = 0, bx2 = 0, bx3 = 0;
        #pragma unroll
        for (int e = 0; e < 48; ++e) {
            float v = cv[tid * 49 + e];
            int   ix = ci[tid * 49 + e];
            if (v < bv3) {
                if (v < bv0) { bv3=bv2b; bx3=bx2; bv2b=bv1b; bx2=bx1; bv1b=bv0; bx1=bx0; bv0=v; bx0=ix; }
                else if (v < bv1b) { bv3=bv2b; bx3=bx2; bv2b=bv1b; bx2=bx1; bv1b=v; bx1=ix; }
                else if (v < bv2b) { bv3=bv2b; bx3=bx2; bv2b=v; bx2=ix; }
                else { bv3=v; bx3=ix; }
            }
        }
        g_cand4[n0 + tid] = make_int4(bx0, bx1, bx2, bx3);
    }
}

// ---------------- exact fp32 rescore of 4 candidates + loss + dw ----------------
__global__ void k_rescore(const float* __restrict__ weight) {
    __shared__ float ls[8];
    const int warp = threadIdx.x >> 5, lane = threadIdx.x & 31;
    float lacc = 0.0f;
    #pragma unroll
    for (int it = 0; it < 4; ++it) {
        int t = (blockIdx.x * 8 + warp) * 4 + it;
        int4 cc = g_cand4[t];
        int cand[4] = {cc.x, cc.y, cc.z, cc.w};
        float xv[8];
        float xn = 0.0f;
        #pragma unroll
        for (int i = 0; i < 8; ++i) {
            xv[i] = g_Xf[(size_t)t * DIM + lane + 32 * i];
            xn += xv[i] * xv[i];
        }
        #pragma unroll
        for (int o = 16; o > 0; o >>= 1) xn += __shfl_xor_sync(0xffffffffu, xn, o);
        float bs = 3.4e38f; int bi = 0x7fffffff;
        #pragma unroll
        for (int j = 0; j < 4; ++j) {
            int k = cand[j];
            float d = 0.0f;
            #pragma unroll
            for (int i = 0; i < 8; ++i)
                d += xv[i] * weight[(size_t)k * DIM + lane + 32 * i];
            #pragma unroll
            for (int o = 16; o > 0; o >>= 1) d += __shfl_xor_sync(0xffffffffu, d, o);
            float s = g_wnorm[k] - 2.0f * d;
            if (s < bs || (s == bs && k < bi)) { bs = s; bi = k; }
        }
        // dw accumulation: all lanes add their x slice (coalesced REDs)
        float* dwr = g_dw + (size_t)bi * DIM + lane;
        #pragma unroll
        for (int i = 0; i < 8; ++i)
            atomicAdd(dwr + 32 * i, xv[i]);
        if (lane == 0) {
            g_idx[t] = bi;
            atomicAdd(&g_counts[bi], 1);
            lacc += bs + xn;          // == ||x - w||^2
        }
    }
    if (lane == 0) ls[warp] = lacc;
    __syncthreads();
    if (threadIdx.x == 0) {
        float s = 0.0f;
        #pragma unroll
        for (int w = 0; w < 8; ++w) s += ls[w];
        atomicAdd(&g_loss, s);
    }
}

// ---------------- quantize: q_out + encodings ----------------
__global__ void __launch_bounds__(256)
k_quant(const float* __restrict__ weight, float* __restrict__ out) {
    __shared__ float wrow[64 * 67];
    __shared__ int   idx_s[64];
    const int tid = threadIdx.x, blk = blockIdx.x;
    const int b = blk >> 6, h = blk & 63;
    const int n0 = b * HW + h * 64;
    if (tid < 64) {
        int ix = g_idx[n0 + tid];
        idx_s[tid] = ix;
        out[OFF_ENC + (long long)(n0 + tid) * KCB + ix] = 1.0f;
    }
    __syncthreads();
    const int w = tid & 63, dg = tid >> 6;
    float* qbp = out + OFF_QOUT + (size_t)b * DHW + h * 64 + w;
    for (int c = 0; c < 4; ++c) {
        #pragma unroll
        for (int p = 0; p < 16; ++p) {
            int idx = tid + p * 256;
            int r = idx >> 6, d = idx & 63;
            wrow[r * 67 + d] = weight[(size_t)idx_s[r] * DIM + c * 64 + d];
        }
        __syncthreads();
        #pragma unroll
        for (int s = 0; s < 16; ++s) {
            int dl = dg * 16 + s;
            int d = c * 64 + dl;
            qbp[(size_t)d * HW] = wrow[w * 67 + dl];
        }
        __syncthreads();
    }
}

// ---------------- stats ----------------
__global__ void k_stats(const float* __restrict__ ecs, float* __restrict__ out) {
    __shared__ float sn[1024];
    __shared__ float sh[1024];
    int t = threadIdx.x;
    float c0 = (float)g_counts[t];
    float c1 = (float)g_counts[t + 1024];
    float cs0 = ecs[t] * DECAYF + OMD * c0;
    float cs1 = ecs[t + 1024] * DECAYF + OMD * c1;
    float p0 = c0 / 65536.0f, p1 = c1 / 65536.0f;
    sn[t] = cs0 + cs1;
    sh[t] = p0 * logf(p0 + 1e-10f) + p1 * logf(p1 + 1e-10f);
    __syncthreads();
    #pragma unroll
    for (int st = 512; st > 0; st >>= 1) {
        if (t < st) { sn[t] += sn[t + st]; sh[t] += sh[t + st]; }
        __syncthreads();
    }
    float n = sn[0];
    float denom = n + (float)KCB * EPSF;
    out[OFF_CS + t]        = (cs0 + EPSF) / denom * n;
    out[OFF_CS + t + 1024] = (cs1 + EPSF) / denom * n;
    if (t == 0) {
        out[OFF_PERP] = expf(-sh[0]);
        out[OFF_LOSS] = 0.25f * g_loss / 16777216.0f;
    }
}

// ---------------- EMA update ----------------
__global__ void k_ema(const float* __restrict__ emaw, float* __restrict__ out) {
    int i = blockIdx.x * 256 + threadIdx.x;
    float e = emaw[i] * DECAYF + OMD * g_dw[i];
    out[OFF_EMAW + i] = e;
    out[OFF_W + i]    = e / out[OFF_CS + (i >> 8)];
}

// ---------------- launch ----------------
extern "C" void kernel_launch(void* const* d_in, const int* in_sizes, int n_in,
                              void* d_out, int out_size) {
    const float* z    = (const float*)d_in[0];
    const float* wgt  = (const float*)d_in[1];
    const float* ecs  = (const float*)d_in[2];
    const float* emaw = (const float*)d_in[3];
    float* out = (float*)d_out;

    cudaFuncSetAttribute(k_gemm,   cudaFuncAttributeMaxDynamicSharedMemorySize, SMT);
    cudaFuncSetAttribute(k_prep_x, cudaFuncAttributeMaxDynamicSharedMemorySize, 64 * 260 * 4);

    k_prep_w <<<256, 256>>>(wgt);
    k_prep_x <<<1024, 256, 64 * 260 * 4>>>(z);
    k_gemm   <<<512, 512, SMT>>>(out);
    k_rescore<<<2048, 256>>>(wgt);
    k_quant  <<<1024, 256>>>(wgt, out);
    k_stats  <<<1, 1024>>>(ecs, out);
    k_ema    <<<2048, 256>>>(emaw, out);
}

// round 10
// speedup vs baseline: 4.2746x; 1.0148x over previous
#include <cuda_runtime.h>
#include <cuda_fp16.h>
#include <math.h>
#include <stdint.h>

// ---------------- problem constants ----------------
#define NTOT   65536
#define KCB    2048
#define DIM    256
#define HW     4096
#define DHW    1048576

#define OFF_LOSS 0LL
#define OFF_QOUT 1LL
#define OFF_PERP 16777217LL
#define OFF_ENC  16777218LL
#define OFF_CS   150994946LL
#define OFF_EMAW 150996994LL
#define OFF_W    151521282LL

static const float DECAYF = 0.99f;
static const float OMD    = 0.01f;
static const float EPSF   = 1e-5f;

// ---------------- device scratch ----------------
__device__ __half g_Xh[NTOT * DIM];     // token-major fp16 x      (32MB)
__device__ __half g_Wh[KCB * DIM];      // code-major fp16 (-2w)   (1MB)
__device__ float  g_Xf[NTOT * DIM];     // token-major fp32 x      (64MB)
__device__ float  g_wnorm[KCB];
__device__ int    g_counts[KCB];
__device__ int4   g_cand4[NTOT];        // 4 exact-rescore candidates per token (1MB)
__device__ float  g_dw[KCB * DIM];
__device__ float  g_loss;

// ---------------- helpers ----------------
__device__ __forceinline__ uint32_t smem_u32(const void* p) {
    uint32_t a;
    asm("{ .reg .u64 t; cvta.to.shared.u64 t, %1; cvt.u32.u64 %0, t; }" : "=r"(a) : "l"(p));
    return a;
}
__device__ __forceinline__ void cp16(uint32_t dst, const void* src) {
    asm volatile("cp.async.cg.shared.global [%0], [%1], 16;" :: "r"(dst), "l"(src) : "memory");
}
__device__ __forceinline__ void cp_commit() { asm volatile("cp.async.commit_group;" ::: "memory"); }

__device__ __forceinline__ void ldm4(uint32_t a, uint32_t r[4]) {
    asm volatile("ldmatrix.sync.aligned.m8n8.x4.shared.b16 {%0,%1,%2,%3}, [%4];"
                 : "=r"(r[0]), "=r"(r[1]), "=r"(r[2]), "=r"(r[3]) : "r"(a));
}
// fp16-accumulate HMMA
__device__ __forceinline__ void mma16816h(uint32_t c[2], const uint32_t a[4],
                                          uint32_t b0, uint32_t b1) {
    asm volatile("mma.sync.aligned.m16n8k16.row.col.f16.f16.f16.f16 "
                 "{%0,%1},{%2,%3,%4,%5},{%6,%7},{%0,%1};"
                 : "+r"(c[0]), "+r"(c[1])
                 : "r"(a[0]), "r"(a[1]), "r"(a[2]), "r"(a[3]), "r"(b0), "r"(b1));
}

// ---------------- codebook prep: fp16(-2w) + norms + init ----------------
__global__ void k_prep_w(const float* __restrict__ weight) {
    int warp = threadIdx.x >> 5, lane = threadIdx.x & 31;
    int k = blockIdx.x * 8 + warp;               // 256 blocks
    float s = 0.0f;
    #pragma unroll
    for (int i = 0; i < 8; ++i) {
        int d = lane + i * 32;
        float v = weight[(size_t)k * DIM + d];
        g_Wh[(size_t)k * DIM + d] = __float2half(-2.0f * v);
        s += v * v;
    }
    #pragma unroll
    for (int o = 16; o > 0; o >>= 1) s += __shfl_down_sync(0xffffffffu, s, o);
    if (lane == 0) {
        g_wnorm[k] = s;
        g_counts[k] = 0;
        if (k == 0) g_loss = 0.0f;
    }
}

// ---------------- x prep: transpose to token-major fp32 + fp16; zero dw ----------------
__global__ void k_prep_x(const float* __restrict__ z) {
    extern __shared__ float xs[];             // 64*260
    const int tid = threadIdx.x;
    // zero g_dw (1024 blocks x 512 elems)
    g_dw[(size_t)blockIdx.x * 512 + tid] = 0.0f;
    g_dw[(size_t)blockIdx.x * 512 + 256 + tid] = 0.0f;

    const int n0 = blockIdx.x * 64;
    const int b = n0 >> 12, sp0 = n0 & 4095;
    const float* zb = z + (size_t)b * DHW + sp0;
    #pragma unroll
    for (int p = 0; p < 16; ++p) {
        int lin = tid + p * 256;
        int q = lin & 63, dq4 = lin >> 6;
        float4 v;
        v.x = zb[(dq4 * 4 + 0) * HW + q];
        v.y = zb[(dq4 * 4 + 1) * HW + q];
        v.z = zb[(dq4 * 4 + 2) * HW + q];
        v.w = zb[(dq4 * 4 + 3) * HW + q];
        *(float4*)(xs + q * 260 + dq4 * 4) = v;
    }
    __syncthreads();
    #pragma unroll
    for (int p = 0; p < 64; ++p) {
        int lin = tid + p * 256;
        int q = lin >> 8, d = lin & 255;
        float v = xs[q * 260 + d];
        size_t t = (size_t)(n0 + q);
        g_Xh[t * DIM + d] = __float2half(v);
        g_Xf[t * DIM + d] = v;
    }
}

// ---------------- HMMA argmin GEMM (fp16 accum) + enc zero-fill ----------------
// 512 CTAs x 512 thr (16 warps: 4m x 4n, warp tile 32x32). CTA = 128 tokens x
// 2048 codes, K=256. A resident (64KB); B double-buffered (2x64KB) cp.async.
// Per-thread top-3; 48 candidates per token merged to top-4.
#define SA  0
#define SB0 65536
#define SB1 131072
#define SMT 196608

__global__ void __launch_bounds__(512, 1)
k_gemm(float* __restrict__ out) {
    extern __shared__ char sm[];
    const uint32_t sb = smem_u32(sm);
    const int tid = threadIdx.x;
    const int lane = tid & 31, warp = tid >> 5;
    const int wm = warp & 3, wn = warp >> 2;      // 4m x 4n
    const int n0 = blockIdx.x * 128;
    float2* enc2 = (float2*)(out + OFF_ENC) + (size_t)blockIdx.x * 131072;

    // A tile (grouped with B0)
    #pragma unroll
    for (int i = 0; i < 8; ++i) {
        int idx = tid + i * 512;                 // 4096 chunks
        int row = idx >> 5, ch = idx & 31;
        cp16(sb + SA + row * 512 + ((ch ^ (row & 7)) << 4),
             g_Xh + (size_t)(n0 + row) * DIM + ch * 8);
    }
    // B tile 0
    #pragma unroll
    for (int i = 0; i < 8; ++i) {
        int idx = tid + i * 512;
        int row = idx >> 5, ch = idx & 31;
        cp16(sb + SB0 + row * 512 + ((ch ^ (row & 7)) << 4),
             g_Wh + (size_t)row * DIM + ch * 8);
    }
    cp_commit();
    // B tile 1
    #pragma unroll
    for (int i = 0; i < 8; ++i) {
        int idx = tid + i * 512;
        int row = idx >> 5, ch = idx & 31;
        cp16(sb + SB1 + row * 512 + ((ch ^ (row & 7)) << 4),
             g_Wh + (size_t)(128 + row) * DIM + ch * 8);
    }
    cp_commit();

    // per-thread top-3 for 4 owned token slots (r = mi*2 + h)
    float v1[4], v2[4], v3[4];
    int   i1[4], i2[4], i3[4];
    #pragma unroll
    for (int r = 0; r < 4; ++r) {
        v1[r] = 3.4e38f; v2[r] = 3.4e38f; v3[r] = 3.4e38f;
        i1[r] = 0; i2[r] = 0; i3[r] = 0;
    }

    const float2 zz = make_float2(0.f, 0.f);

    for (int nt = 0; nt < 16; ++nt) {
        if (nt < 15) asm volatile("cp.async.wait_group 1;" ::: "memory");
        else         asm volatile("cp.async.wait_group 0;" ::: "memory");
        __syncthreads();
        const uint32_t BB = sb + ((nt & 1) ? SB1 : SB0);

        uint32_t c[2][4][2];
        #pragma unroll
        for (int mi = 0; mi < 2; ++mi)
            #pragma unroll
            for (int ni = 0; ni < 4; ++ni) { c[mi][ni][0] = 0u; c[mi][ni][1] = 0u; }

        #pragma unroll
        for (int ks = 0; ks < 16; ++ks) {
            uint32_t a[2][4];
            #pragma unroll
            for (int mi = 0; mi < 2; ++mi) {
                int row = wm * 32 + mi * 16 + (lane & 15);
                int ch = ks * 2 + (lane >> 4);
                ldm4(sb + SA + row * 512 + ((ch ^ (row & 7)) << 4), a[mi]);
            }
            // B: non-trans ldmatrix on code-major smem; two 16-code groups.
            uint32_t b0[4], b1[4];
            {
                int code = wn * 32 + ((lane & 16) >> 1) + (lane & 7);
                int ch = ks * 2 + ((lane >> 3) & 1);
                ldm4(BB + code * 512 + ((ch ^ (code & 7)) << 4), b0);
                code += 16;
                ldm4(BB + code * 512 + ((ch ^ (code & 7)) << 4), b1);
            }
            #pragma unroll
            for (int mi = 0; mi < 2; ++mi) {
                mma16816h(c[mi][0], a[mi], b0[0], b0[1]);
                mma16816h(c[mi][1], a[mi], b0[2], b0[3]);
                mma16816h(c[mi][2], a[mi], b1[0], b1[1]);
                mma16816h(c[mi][3], a[mi], b1[2], b1[3]);
            }
        }

        // zero 16 float2 chunks of this CTA's encodings slice (streaming, 8B-aligned)
        #pragma unroll
        for (int j = 0; j < 16; ++j)
            __stcs(enc2 + (size_t)(nt * 16 + j) * 512 + tid, zz);

        // fold: score = wnorm + acc  (acc = x . (-2w), fp16 pair); top-3 insert
        #pragma unroll
        for (int ni = 0; ni < 4; ++ni) {
            int col = nt * 128 + wn * 32 + ni * 8 + (lane & 3) * 2;
            float2 wn2 = *(const float2*)&g_wnorm[col];
            #pragma unroll
            for (int mi = 0; mi < 2; ++mi) {
                #pragma unroll
                for (int h = 0; h < 2; ++h) {
                    int r = mi * 2 + h;
                    float2 cf = __half22float2(*(__half2*)&c[mi][ni][h]);
                    float s0 = wn2.x + cf.x;
                    float s1 = wn2.y + cf.y;
                    if (s0 < v3[r]) {
                        if (s0 < v1[r]) { v3[r]=v2[r]; i3[r]=i2[r]; v2[r]=v1[r]; i2[r]=i1[r]; v1[r]=s0; i1[r]=col; }
                        else if (s0 < v2[r]) { v3[r]=v2[r]; i3[r]=i2[r]; v2[r]=s0; i2[r]=col; }
                        else { v3[r]=s0; i3[r]=col; }
                    }
                    if (s1 < v3[r]) {
                        if (s1 < v1[r]) { v3[r]=v2[r]; i3[r]=i2[r]; v2[r]=v1[r]; i2[r]=i1[r]; v1[r]=s1; i1[r]=col+1; }
                        else if (s1 < v2[r]) { v3[r]=v2[r]; i3[r]=i2[r]; v2[r]=s1; i2[r]=col+1; }
                        else { v3[r]=s1; i3[r]=col+1; }
                    }
                }
            }
        }

        __syncthreads();
        if (nt + 2 < 16) {
            const uint32_t NB = sb + ((nt & 1) ? SB1 : SB0);
            #pragma unroll
            for (int i = 0; i < 8; ++i) {
                int idx = tid + i * 512;
                int row = idx >> 5, ch = idx & 31;
                cp16(NB + row * 512 + ((ch ^ (row & 7)) << 4),
                     g_Wh + (size_t)((nt + 2) * 128 + row) * DIM + ch * 8);
            }
            cp_commit();
        }
    }

    // ---- per-token merge: 16 threads x top-3 -> global top-4 (smem, stride 49) ----
    __syncthreads();
    float* cv = (float*)sm;                      // 128 * 49 floats (25088 B)
    int*   ci = (int*)(sm + 25088);              // 128 * 49 ints
    const int slot = wn * 4 + (lane & 3);        // 0..15
    #pragma unroll
    for (int mi = 0; mi < 2; ++mi)
        #pragma unroll
        for (int h = 0; h < 2; ++h) {
            int r = mi * 2 + h;
            int tloc = wm * 32 + mi * 16 + h * 8 + (lane >> 2);
            cv[tloc * 49 + slot * 3 + 0] = v1[r];  ci[tloc * 49 + slot * 3 + 0] = i1[r];
            cv[tloc * 49 + slot * 3 + 1] = v2[r];  ci[tloc * 49 + slot * 3 + 1] = i2[r];
            cv[tloc * 49 + slot * 3 + 2] = v3[r];  ci[tloc * 49 + slot * 3 + 2] = i3[r];
        }
    __syncthreads();
    if (tid < 128) {
        float bv0 = 3.4e38f, bv1b = 3.4e38f, bv2b = 3.4e38f, bv3 = 3.4e38f;
        int   bx0 = 0, bx1 = 0, bx2 = 0, bx3 = 0;
        #pragma unroll
        for (int e = 0; e < 48; ++e) {
            float v = cv[tid * 49 + e];
            int   ix = ci[tid * 49 + e];
            if (v < bv3) {
                if (v < bv0) { bv3=bv2b; bx3=bx2; bv2b=bv1b; bx2=bx1; bv1b=bv0; bx1=bx0; bv0=v; bx0=ix; }
                else if (v < bv1b) { bv3=bv2b; bx3=bx2; bv2b=bv1b; bx2=bx1; bv1b=v; bx1=ix; }
                else if (v < bv2b) { bv3=bv2b; bx3=bx2; bv2b=v; bx2=ix; }
                else { bv3=v; bx3=ix; }
            }
        }
        g_cand4[n0 + tid] = make_int4(bx0, bx1, bx2, bx3);
    }
}

// ---------------- fused: exact rescore + loss + dw + encodings + q_out ----------------
// 1024 blocks (one per 64-token row) x 512 thr. Warp w owns tokens w*4..w*4+3.
__global__ void __launch_bounds__(512)
k_resq(const float* __restrict__ weight, float* __restrict__ out) {
    __shared__ float wrow[64 * 67];
    __shared__ int   idx_s[64];
    __shared__ float ls[16];
    const int tid = threadIdx.x;
    const int warp = tid >> 5, lane = tid & 31;
    const int blk = blockIdx.x;
    const int b = blk >> 6, h = blk & 63;
    const int n0 = b * HW + h * 64;

    float lacc = 0.0f;
    #pragma unroll
    for (int it = 0; it < 4; ++it) {
        int tok = n0 + warp * 4 + it;
        int4 cc = g_cand4[tok];
        const float* w0 = weight + (size_t)cc.x * DIM + lane;
        const float* w1 = weight + (size_t)cc.y * DIM + lane;
        const float* w2 = weight + (size_t)cc.z * DIM + lane;
        const float* w3 = weight + (size_t)cc.w * DIM + lane;
        float xv[8];
        float xn = 0.0f;
        float d0 = 0.0f, d1 = 0.0f, d2 = 0.0f, d3 = 0.0f;
        #pragma unroll
        for (int i = 0; i < 8; ++i) {
            xv[i] = g_Xf[(size_t)tok * DIM + lane + 32 * i];
            xn += xv[i] * xv[i];
        }
        #pragma unroll
        for (int i = 0; i < 8; ++i) {
            float a0 = __ldg(w0 + 32 * i);
            float a1 = __ldg(w1 + 32 * i);
            float a2 = __ldg(w2 + 32 * i);
            float a3 = __ldg(w3 + 32 * i);
            d0 += xv[i] * a0;
            d1 += xv[i] * a1;
            d2 += xv[i] * a2;
            d3 += xv[i] * a3;
        }
        #pragma unroll
        for (int o = 16; o > 0; o >>= 1) {
            xn += __shfl_xor_sync(0xffffffffu, xn, o);
            d0 += __shfl_xor_sync(0xffffffffu, d0, o);
            d1 += __shfl_xor_sync(0xffffffffu, d1, o);
            d2 += __shfl_xor_sync(0xffffffffu, d2, o);
            d3 += __shfl_xor_sync(0xffffffffu, d3, o);
        }
        float s0 = g_wnorm[cc.x] - 2.0f * d0;
        float s1 = g_wnorm[cc.y] - 2.0f * d1;
        float s2 = g_wnorm[cc.z] - 2.0f * d2;
        float s3 = g_wnorm[cc.w] - 2.0f * d3;
        float bs = s0; int bi = cc.x;
        if (s1 < bs || (s1 == bs && cc.y < bi)) { bs = s1; bi = cc.y; }
        if (s2 < bs || (s2 == bs && cc.z < bi)) { bs = s2; bi = cc.z; }
        if (s3 < bs || (s3 == bs && cc.w < bi)) { bs = s3; bi = cc.w; }
        // dw accumulation (coalesced REDs)
        float* dwr = g_dw + (size_t)bi * DIM + lane;
        #pragma unroll
        for (int i = 0; i < 8; ++i)
            atomicAdd(dwr + 32 * i, xv[i]);
        if (lane == 0) {
            idx_s[warp * 4 + it] = bi;
            atomicAdd(&g_counts[bi], 1);
            out[OFF_ENC + (long long)tok * KCB + bi] = 1.0f;
            lacc += bs + xn;          // == ||x - w||^2
        }
    }
    if (lane == 0) ls[warp] = lacc;
    __syncthreads();
    if (tid == 0) {
        float s = 0.0f;
        #pragma unroll
        for (int w = 0; w < 16; ++w) s += ls[w];
        atomicAdd(&g_loss, s);
    }

    // ---- quant phase: stage gathered rows, write q_out coalesced ----
    const int w = tid & 63, dg = tid >> 6;       // dg 0..7
    float* qbp = out + OFF_QOUT + (size_t)b * DHW + h * 64 + w;
    for (int c = 0; c < 4; ++c) {
        #pragma unroll
        for (int p = 0; p < 8; ++p) {
            int idx = tid + p * 512;
            int r = idx >> 6, d = idx & 63;
            wrow[r * 67 + d] = __ldg(weight + (size_t)idx_s[r] * DIM + c * 64 + d);
        }
        __syncthreads();
        #pragma unroll
        for (int s = 0; s < 8; ++s) {
            int dl = dg * 8 + s;
            int d = c * 64 + dl;
            __stcs(qbp + (size_t)d * HW, wrow[w * 67 + dl]);
        }
        __syncthreads();
    }
}

// ---------------- stats ----------------
__global__ void k_stats(const float* __restrict__ ecs, float* __restrict__ out) {
    __shared__ float sn[1024];
    __shared__ float sh[1024];
    int t = threadIdx.x;
    float c0 = (float)g_counts[t];
    float c1 = (float)g_counts[t + 1024];
    float cs0 = ecs[t] * DECAYF + OMD * c0;
    float cs1 = ecs[t + 1024] * DECAYF + OMD * c1;
    float p0 = c0 / 65536.0f, p1 = c1 / 65536.0f;
    sn[t] = cs0 + cs1;
    sh[t] = p0 * logf(p0 + 1e-10f) + p1 * logf(p1 + 1e-10f);
    __syncthreads();
    #pragma unroll
    for (int st = 512; st > 0; st >>= 1) {
        if (t < st) { sn[t] += sn[t + st]; sh[t] += sh[t + st]; }
        __syncthreads();
    }
    float n = sn[0];
    float denom = n + (float)KCB * EPSF;
    out[OFF_CS + t]        = (cs0 + EPSF) / denom * n;
    out[OFF_CS + t + 1024] = (cs1 + EPSF) / denom * n;
    if (t == 0) {
        out[OFF_PERP] = expf(-sh[0]);
        out[OFF_LOSS] = 0.25f * g_loss / 16777216.0f;
    }
}

// ---------------- EMA update ----------------
__global__ void k_ema(const float* __restrict__ emaw, float* __restrict__ out) {
    int i = blockIdx.x * 256 + threadIdx.x;
    float e = emaw[i] * DECAYF + OMD * g_dw[i];
    out[OFF_EMAW + i] = e;
    out[OFF_W + i]    = e / out[OFF_CS + (i >> 8)];
}

// ---------------- launch ----------------
extern "C" void kernel_launch(void* const* d_in, const int* in_sizes, int n_in,
                              void* d_out, int out_size) {
    const float* z    = (const float*)d_in[0];
    const float* wgt  = (const float*)d_in[1];
    const float* ecs  = (const float*)d_in[2];
    const float* emaw = (const float*)d_in[3];
    float* out = (float*)d_out;

    cudaFuncSetAttribute(k_gemm,   cudaFuncAttributeMaxDynamicSharedMemorySize, SMT);
    cudaFuncSetAttribute(k_prep_x, cudaFuncAttributeMaxDynamicSharedMemorySize, 64 * 260 * 4);

    k_prep_w <<<256, 256>>>(wgt);
    k_prep_x <<<1024, 256, 64 * 260 * 4>>>(z);
    k_gemm   <<<512, 512, SMT>>>(out);
    k_resq   <<<1024, 512>>>(wgt, out);
    k_stats  <<<1, 1024>>>(ecs, out);
    k_ema    <<<2048, 256>>>(emaw, out);
}